// round 14
// baseline (speedup 1.0000x reference)
#include <cuda_runtime.h>
#include <cuda_fp16.h>
#include <math.h>
#include <stdint.h>

#define kN   32768
#define kE   (kN * 16)
#define kD   256
#define kH   8
#define kDH  32
#define kTD  256
#define kFFN 1024
#define kL   2
#define kQKV 768

// ---------------- device scratch ----------------
__device__ __half g_xh  [kN * kD];
__device__ __half g_xnh [kN * kD];
__device__ __half g_qh  [kN * kTD];
__device__ __half g_kh  [kN * kTD];
__device__ __half g_vh  [kN * kTD];
__device__ __half g_aggh[kN * kTD];
__device__ __half g_ffnh[kN * kFFN];
__device__ __half g_winT [kD * kD];
__device__ __half g_wqkvT[kL * kQKV * kD];
__device__ __half g_woT  [kL * kD * kTD];
__device__ __half g_w1T  [kL * kFFN * kD];
__device__ __half g_w2T  [kL * kD * kFFN];
__device__ float  g_bqkv [kL * kQKV];
__device__ int    g_deg [kN];
__device__ int    g_fill[kN];
__device__ int    g_off [kN + 1];
__device__ int    g_csr [kE];

// ---------------- helpers ----------------
__device__ __forceinline__ uint32_t smem_u32(const void* p) {
    uint32_t a;
    asm("{ .reg .u64 t; cvta.to.shared.u64 t, %1; cvt.u32.u64 %0, t; }" : "=r"(a) : "l"(p));
    return a;
}
__device__ __forceinline__ void mma_f16(float& d0, float& d1, float& d2, float& d3,
                                        uint32_t a0, uint32_t a1, uint32_t a2, uint32_t a3,
                                        uint32_t b0, uint32_t b1) {
    asm volatile("mma.sync.aligned.m16n8k16.row.col.f32.f16.f16.f32 "
                 "{%0,%1,%2,%3}, {%4,%5,%6,%7}, {%8,%9}, {%0,%1,%2,%3};"
                 : "+f"(d0), "+f"(d1), "+f"(d2), "+f"(d3)
                 : "r"(a0), "r"(a1), "r"(a2), "r"(a3), "r"(b0), "r"(b1));
}
__device__ __forceinline__ void ldsm_x4(uint4& r, uint32_t addr) {
    asm volatile("ldmatrix.sync.aligned.m8n8.x4.shared.b16 {%0,%1,%2,%3}, [%4];"
                 : "=r"(r.x), "=r"(r.y), "=r"(r.z), "=r"(r.w) : "r"(addr));
}
__device__ __forceinline__ void cp16(uint32_t saddr, const void* gaddr) {
    asm volatile("cp.async.cg.shared.global [%0], [%1], 16;" :: "r"(saddr), "l"(gaddr));
}
__device__ __forceinline__ float gelu_exact(float x) {
    return 0.5f * x * (1.f + erff(x * 0.7071067811865475f));
}

// ---------------- fp16 cp.async+ldmatrix GEMM: C = A[M,K] @ Bt[N,K]^T -----
// Block 128x256, 8 warps (2x4), warp tile 64x64, BK=32, 3-stage cp.async ring.
#define BM 128
#define BN 256
#define BK 32
#define ATILE_B (BM * BK * 2)            // 8192
#define BTILE_B (BN * BK * 2)            // 16384
#define STAGE_B (ATILE_B + BTILE_B)      // 24576
#define NSTAGE 3
#define DSMEM (NSTAGE * STAGE_B)         // 73728

__global__ void __launch_bounds__(256, 1)
gemm_tc(const __half* __restrict__ A, const __half* __restrict__ Bt,
        const float* __restrict__ bias, float* __restrict__ C,
        __half* __restrict__ aux, __half* __restrict__ aux2,
        int M, int N, int K, int flags) {
    extern __shared__ char dsm[];
    uint32_t sbase = smem_u32(dsm);

    int tid = threadIdx.x;
    int lane = tid & 31;
    int wid = tid >> 5;
    int warp_row = wid >> 2;       // 0..1 (64-row halves)
    int warp_col = wid & 3;        // 0..3 (64-col quarters)
    int row0 = blockIdx.y * BM, col0 = blockIdx.x * BN;

    const __half* Ag = A + (size_t)row0 * K;
    const __half* Bg = Bt + (size_t)col0 * K;

    // copy indices: thread t handles A chunks {2t,2t+1} and B chunks
    // {2t,2t+1, 512+2t,512+2t+1} (B's +512 chunk = +128 rows, same swizzle)
    int id0 = tid * 2;
    int crow0 = id0 >> 2,       cc0 = id0 & 3;
    int crow1 = (id0 + 1) >> 2, cc1 = (id0 + 1) & 3;
    int cs0 = cc0 ^ ((crow0 >> 1) & 3);
    int cs1 = cc1 ^ ((crow1 >> 1) & 3);
    uint32_t sA0 = crow0 * 64 + cs0 * 16;
    uint32_t sA1 = crow1 * 64 + cs1 * 16;
    size_t gA0 = (size_t)crow0 * K + cc0 * 8;
    size_t gA1 = (size_t)crow1 * K + cc1 * 8;
    size_t gB2 = gA0 + (size_t)128 * K;
    size_t gB3 = gA1 + (size_t)128 * K;

    int lane_r = lane & 15;
    int lane_c = lane >> 4;
    int xorv = (lane_r >> 1) & 3;

    float acc[4][8][4];
    #pragma unroll
    for (int i = 0; i < 4; ++i)
        #pragma unroll
        for (int j = 0; j < 8; ++j)
            #pragma unroll
            for (int q = 0; q < 4; ++q) acc[i][j][q] = 0.f;

    int nIter = K / BK;

    // prologue: issue 2 stages
    #pragma unroll
    for (int s = 0; s < 2; ++s) {
        uint32_t Ab = sbase + s * STAGE_B;
        uint32_t Bb = Ab + ATILE_B;
        int kk = s * BK;
        cp16(Ab + sA0, Ag + gA0 + kk);
        cp16(Ab + sA1, Ag + gA1 + kk);
        cp16(Bb + sA0, Bg + gA0 + kk);
        cp16(Bb + sA1, Bg + gA1 + kk);
        cp16(Bb + sA0 + 8192, Bg + gB2 + kk);
        cp16(Bb + sA1 + 8192, Bg + gB3 + kk);
        asm volatile("cp.async.commit_group;");
    }

    int stage = 0;
    for (int it = 0; it < nIter; ++it) {
        asm volatile("cp.async.wait_group 1;");
        __syncthreads();
        uint32_t Ab = sbase + stage * STAGE_B;
        uint32_t Bb = Ab + ATILE_B;

        #pragma unroll
        for (int kc = 0; kc < 2; ++kc) {
            uint32_t cs = (uint32_t)(((kc * 2 + lane_c) ^ xorv) * 16);
            uint4 af[4], bm[4];
            #pragma unroll
            for (int mt = 0; mt < 4; ++mt)
                ldsm_x4(af[mt], Ab + (uint32_t)(warp_row * 64 + mt * 16 + lane_r) * 64 + cs);
            #pragma unroll
            for (int ntp = 0; ntp < 4; ++ntp)
                ldsm_x4(bm[ntp], Bb + (uint32_t)(warp_col * 64 + ntp * 16 + lane_r) * 64 + cs);
            #pragma unroll
            for (int mt = 0; mt < 4; ++mt)
                #pragma unroll
                for (int ntp = 0; ntp < 4; ++ntp) {
                    mma_f16(acc[mt][2*ntp][0], acc[mt][2*ntp][1], acc[mt][2*ntp][2], acc[mt][2*ntp][3],
                            af[mt].x, af[mt].y, af[mt].z, af[mt].w, bm[ntp].x, bm[ntp].z);
                    mma_f16(acc[mt][2*ntp+1][0], acc[mt][2*ntp+1][1], acc[mt][2*ntp+1][2], acc[mt][2*ntp+1][3],
                            af[mt].x, af[mt].y, af[mt].z, af[mt].w, bm[ntp].y, bm[ntp].w);
                }
        }
        if (it + 2 < nIter) {
            int ws = stage + 2;
            if (ws >= NSTAGE) ws -= NSTAGE;
            uint32_t Aw = sbase + ws * STAGE_B;
            uint32_t Bw = Aw + ATILE_B;
            int kk = (it + 2) * BK;
            cp16(Aw + sA0, Ag + gA0 + kk);
            cp16(Aw + sA1, Ag + gA1 + kk);
            cp16(Bw + sA0, Bg + gA0 + kk);
            cp16(Bw + sA1, Bg + gA1 + kk);
            cp16(Bw + sA0 + 8192, Bg + gB2 + kk);
            cp16(Bw + sA1 + 8192, Bg + gB3 + kk);
        }
        asm volatile("cp.async.commit_group;");
        if (++stage == NSTAGE) stage = 0;
    }

    // ---- epilogue ----
    int g = lane >> 2, tg = lane & 3;
    bool isq = (col0 == 0);
    bool isv = (col0 >= 512);
    #pragma unroll
    for (int mt = 0; mt < 4; ++mt) {
        int rbase = row0 + warp_row * 64 + mt * 16 + g;
        #pragma unroll
        for (int nt = 0; nt < 8; ++nt) {
            int c = col0 + warp_col * 64 + nt * 8 + tg * 2;
            float2 bs = *reinterpret_cast<const float2*>(&bias[c]);
            float v0 = acc[mt][nt][0] + bs.x;
            float v1 = acc[mt][nt][1] + bs.y;
            float v2 = acc[mt][nt][2] + bs.x;
            float v3 = acc[mt][nt][3] + bs.y;
            if (flags == 2) {
                v0 = gelu_exact(v0); v1 = gelu_exact(v1);
                v2 = gelu_exact(v2); v3 = gelu_exact(v3);
                *reinterpret_cast<__half2*>(aux + (size_t)rbase * N + c)       = __floats2half2_rn(v0, v1);
                *reinterpret_cast<__half2*>(aux + (size_t)(rbase + 8) * N + c) = __floats2half2_rn(v2, v3);
            } else if (flags == 3) {
                __half* dst = isq ? reinterpret_cast<__half*>(C) : (isv ? aux2 : aux);
                int cm = c & 255;
                *reinterpret_cast<__half2*>(dst + (size_t)rbase * kTD + cm)       = __floats2half2_rn(v0, v1);
                *reinterpret_cast<__half2*>(dst + (size_t)(rbase + 8) * kTD + cm) = __floats2half2_rn(v2, v3);
            } else {
                float2* cp0 = reinterpret_cast<float2*>(C + (size_t)rbase * N + c);
                float2* cp1 = reinterpret_cast<float2*>(C + (size_t)(rbase + 8) * N + c);
                if (flags == 1) {
                    float2 o0 = *cp0, o1 = *cp1;
                    v0 += o0.x; v1 += o0.y; v2 += o1.x; v3 += o1.y;
                }
                float2 r0 = {v0, v1}, r1 = {v2, v3};
                *cp0 = r0;
                *cp1 = r1;
            }
        }
    }
}

// ---------------- transpose + fp32->fp16 ----------------
__global__ void transpose_h(const float* __restrict__ src, __half* __restrict__ dst,
                            int R, int C) {
    __shared__ float t[32][33];
    int bx = blockIdx.x * 32, by = blockIdx.y * 32;
    int x = bx + threadIdx.x;
    #pragma unroll
    for (int j = 0; j < 32; j += 8)
        t[threadIdx.y + j][threadIdx.x] = src[(size_t)(by + threadIdx.y + j) * C + x];
    __syncthreads();
    int xo = by + threadIdx.x;
    #pragma unroll
    for (int j = 0; j < 32; j += 8)
        dst[(size_t)(bx + threadIdx.y + j) * R + xo] = __float2half_rn(t[threadIdx.x][threadIdx.y + j]);
}
__global__ void transpose3_h(const float* s0, const float* s1, const float* s2,
                             __half* __restrict__ dst, int R, int C) {
    __shared__ float t[32][33];
    const float* src = (blockIdx.z == 0) ? s0 : (blockIdx.z == 1) ? s1 : s2;
    __half* d = dst + (size_t)blockIdx.z * C * R;
    int bx = blockIdx.x * 32, by = blockIdx.y * 32;
    int x = bx + threadIdx.x;
    #pragma unroll
    for (int j = 0; j < 32; j += 8)
        t[threadIdx.y + j][threadIdx.x] = src[(size_t)(by + threadIdx.y + j) * C + x];
    __syncthreads();
    int xo = by + threadIdx.x;
    #pragma unroll
    for (int j = 0; j < 32; j += 8)
        d[(size_t)(bx + threadIdx.y + j) * R + xo] = __float2half_rn(t[threadIdx.x][threadIdx.y + j]);
}

__global__ void cvt_x(const float* __restrict__ x, __half* __restrict__ xh) {
    int i = blockIdx.x * 256 + threadIdx.x;
    float4 v = reinterpret_cast<const float4*>(x)[i];
    __half2 h0 = __floats2half2_rn(v.x, v.y);
    __half2 h1 = __floats2half2_rn(v.z, v.w);
    uint2 u = {*reinterpret_cast<uint32_t*>(&h0), *reinterpret_cast<uint32_t*>(&h1)};
    reinterpret_cast<uint2*>(xh)[i] = u;
}

__global__ void pack_bias(const float* bq, const float* bk, const float* bv) {
    int t = blockIdx.x * 256 + threadIdx.x;
    int l = t / kQKV, r = t % kQKV;
    const float* s = (r < 256) ? bq + l * kTD + r
                   : (r < 512) ? bk + l * kTD + (r - 256)
                               : bv + l * kTD + (r - 512);
    g_bqkv[t] = *s;
}

// ---------------- CSR build ----------------
__global__ void deg_count_kernel(const int* __restrict__ ei) {
    int e = blockIdx.x * 256 + threadIdx.x;
    if (e < kE) atomicAdd(&g_deg[ei[kE + e]], 1);
}
__global__ void prefix_kernel() {
    __shared__ int sums[1024];
    int t = threadIdx.x;
    int base = t * 32;
    int s = 0;
    #pragma unroll 4
    for (int i = 0; i < 32; ++i) s += g_deg[base + i];
    sums[t] = s;
    __syncthreads();
    for (int o = 1; o < 1024; o <<= 1) {
        int v = (t >= o) ? sums[t - o] : 0;
        __syncthreads();
        sums[t] += v;
        __syncthreads();
    }
    int run = sums[t] - s;
    for (int i = 0; i < 32; ++i) { g_off[base + i] = run; run += g_deg[base + i]; }
    if (t == 1023) g_off[kN] = run;
}
__global__ void scatter_kernel(const int* __restrict__ ei) {
    int e = blockIdx.x * 256 + threadIdx.x;
    if (e < kE) {
        int d = ei[kE + e];
        int pos = g_off[d] + atomicAdd(&g_fill[d], 1);
        g_csr[pos] = ei[e];
    }
}

// ---------------- LayerNorm: warp per row, fp32 in, fp16 out --------------
__global__ void __launch_bounds__(256)
ln_kernel(const float* __restrict__ x, const float* __restrict__ gg,
          const float* __restrict__ bb, __half* __restrict__ y) {
    int lane = threadIdx.x & 31;
    int row = blockIdx.x * 8 + (threadIdx.x >> 5);
    const float4* xr = reinterpret_cast<const float4*>(x + (size_t)row * kD);
    float4 a0 = xr[lane];
    float4 a1 = xr[lane + 32];
    float s = a0.x + a0.y + a0.z + a0.w + a1.x + a1.y + a1.z + a1.w;
    float q = a0.x*a0.x + a0.y*a0.y + a0.z*a0.z + a0.w*a0.w
            + a1.x*a1.x + a1.y*a1.y + a1.z*a1.z + a1.w*a1.w;
    #pragma unroll
    for (int o = 16; o; o >>= 1) {
        s += __shfl_xor_sync(~0u, s, o);
        q += __shfl_xor_sync(~0u, q, o);
    }
    float mean = s * (1.f / kD);
    float var = q * (1.f / kD) - mean * mean;
    float inv = rsqrtf(var + 1e-5f);
    float4 g0 = reinterpret_cast<const float4*>(gg)[lane];
    float4 g1 = reinterpret_cast<const float4*>(gg)[lane + 32];
    float4 b0 = reinterpret_cast<const float4*>(bb)[lane];
    float4 b1 = reinterpret_cast<const float4*>(bb)[lane + 32];
    __half2 o0 = __floats2half2_rn((a0.x - mean) * inv * g0.x + b0.x, (a0.y - mean) * inv * g0.y + b0.y);
    __half2 o1 = __floats2half2_rn((a0.z - mean) * inv * g0.z + b0.z, (a0.w - mean) * inv * g0.w + b0.w);
    __half2 o2 = __floats2half2_rn((a1.x - mean) * inv * g1.x + b1.x, (a1.y - mean) * inv * g1.y + b1.y);
    __half2 o3 = __floats2half2_rn((a1.z - mean) * inv * g1.z + b1.z, (a1.w - mean) * inv * g1.w + b1.w);
    uint2 u0 = {*reinterpret_cast<uint32_t*>(&o0), *reinterpret_cast<uint32_t*>(&o1)};
    uint2 u1 = {*reinterpret_cast<uint32_t*>(&o2), *reinterpret_cast<uint32_t*>(&o3)};
    *reinterpret_cast<uint2*>(y + (size_t)row * kD + lane * 4)       = u0;
    *reinterpret_cast<uint2*>(y + (size_t)row * kD + 128 + lane * 4) = u1;
}

// ------- Edge attention: warp = 4 heads, lane = 4 dims, 3-shfl reduce -----
__global__ void __launch_bounds__(256)
attn_kernel() {
    int tid = threadIdx.x;
    int lane = tid & 31;
    int wid = tid >> 5;
    int node = blockIdx.x * 4 + (wid >> 1);
    int head = ((wid & 1) << 2) + (lane >> 3);
    int d0 = (lane & 7) << 2;
    int base = node * kTD + head * kDH + d0;

    int beg = g_off[node], end = g_off[node + 1];
    uint2* outp = reinterpret_cast<uint2*>(g_aggh + base);
    if (beg == end) { uint2 z = {0u, 0u}; *outp = z; return; }

    uint2 qu = *reinterpret_cast<const uint2*>(g_qh + base);
    float2 qa = __half22float2(*reinterpret_cast<const __half2*>(&qu.x));
    float2 qb = __half22float2(*reinterpret_cast<const __half2*>(&qu.y));
    const float sc = 0.17677669529663687f;
    float q0 = qa.x * sc, q1 = qa.y * sc, q2 = qb.x * sc, q3 = qb.y * sc;

    float l = 0.f, a0 = 0.f, a1 = 0.f, a2 = 0.f, a3 = 0.f;
    int hoff = head * kDH + d0;

    {
        uint2 ku = *reinterpret_cast<const uint2*>(g_kh + base);
        uint2 vu = *reinterpret_cast<const uint2*>(g_vh + base);
        float2 ka = __half22float2(*reinterpret_cast<const __half2*>(&ku.x));
        float2 kb = __half22float2(*reinterpret_cast<const __half2*>(&ku.y));
        float s = q0 * ka.x + q1 * ka.y + q2 * kb.x + q3 * kb.y;
        s += __shfl_xor_sync(~0u, s, 4);
        s += __shfl_xor_sync(~0u, s, 2);
        s += __shfl_xor_sync(~0u, s, 1);
        float p = __expf(s);
        float2 va = __half22float2(*reinterpret_cast<const __half2*>(&vu.x));
        float2 vb = __half22float2(*reinterpret_cast<const __half2*>(&vu.y));
        l += p; a0 += p * va.x; a1 += p * va.y; a2 += p * vb.x; a3 += p * vb.y;
    }
    int i = beg;
    for (; i + 1 < end; i += 2) {
        int s0 = g_csr[i], s1 = g_csr[i + 1];
        const __half* k0p = g_kh + (size_t)s0 * kTD + hoff;
        const __half* k1p = g_kh + (size_t)s1 * kTD + hoff;
        const __half* v0p = g_vh + (size_t)s0 * kTD + hoff;
        const __half* v1p = g_vh + (size_t)s1 * kTD + hoff;
        uint2 k0u = *reinterpret_cast<const uint2*>(k0p);
        uint2 k1u = *reinterpret_cast<const uint2*>(k1p);
        uint2 v0u = *reinterpret_cast<const uint2*>(v0p);
        uint2 v1u = *reinterpret_cast<const uint2*>(v1p);
        float2 k0a = __half22float2(*reinterpret_cast<const __half2*>(&k0u.x));
        float2 k0b = __half22float2(*reinterpret_cast<const __half2*>(&k0u.y));
        float2 k1a = __half22float2(*reinterpret_cast<const __half2*>(&k1u.x));
        float2 k1b = __half22float2(*reinterpret_cast<const __half2*>(&k1u.y));
        float sa = q0 * k0a.x + q1 * k0a.y + q2 * k0b.x + q3 * k0b.y;
        float sb = q0 * k1a.x + q1 * k1a.y + q2 * k1b.x + q3 * k1b.y;
        sa += __shfl_xor_sync(~0u, sa, 4); sb += __shfl_xor_sync(~0u, sb, 4);
        sa += __shfl_xor_sync(~0u, sa, 2); sb += __shfl_xor_sync(~0u, sb, 2);
        sa += __shfl_xor_sync(~0u, sa, 1); sb += __shfl_xor_sync(~0u, sb, 1);
        float p0 = __expf(sa), p1 = __expf(sb);
        float2 v0a = __half22float2(*reinterpret_cast<const __half2*>(&v0u.x));
        float2 v0b = __half22float2(*reinterpret_cast<const __half2*>(&v0u.y));
        float2 v1a = __half22float2(*reinterpret_cast<const __half2*>(&v1u.x));
        float2 v1b = __half22float2(*reinterpret_cast<const __half2*>(&v1u.y));
        l += p0 + p1;
        a0 += p0 * v0a.x + p1 * v1a.x;
        a1 += p0 * v0a.y + p1 * v1a.y;
        a2 += p0 * v0b.x + p1 * v1b.x;
        a3 += p0 * v0b.y + p1 * v1b.y;
    }
    if (i < end) {
        int s0 = g_csr[i];
        const __half* kp = g_kh + (size_t)s0 * kTD + hoff;
        const __half* vp = g_vh + (size_t)s0 * kTD + hoff;
        uint2 ku = *reinterpret_cast<const uint2*>(kp);
        uint2 vu = *reinterpret_cast<const uint2*>(vp);
        float2 ka = __half22float2(*reinterpret_cast<const __half2*>(&ku.x));
        float2 kb = __half22float2(*reinterpret_cast<const __half2*>(&ku.y));
        float s = q0 * ka.x + q1 * ka.y + q2 * kb.x + q3 * kb.y;
        s += __shfl_xor_sync(~0u, s, 4);
        s += __shfl_xor_sync(~0u, s, 2);
        s += __shfl_xor_sync(~0u, s, 1);
        float p = __expf(s);
        float2 va = __half22float2(*reinterpret_cast<const __half2*>(&vu.x));
        float2 vb = __half22float2(*reinterpret_cast<const __half2*>(&vu.y));
        l += p; a0 += p * va.x; a1 += p * va.y; a2 += p * vb.x; a3 += p * vb.y;
    }
    float inv = 1.f / l;
    __half2 o0 = __floats2half2_rn(a0 * inv, a1 * inv);
    __half2 o1 = __floats2half2_rn(a2 * inv, a3 * inv);
    uint2 ou = {*reinterpret_cast<uint32_t*>(&o0), *reinterpret_cast<uint32_t*>(&o1)};
    *outp = ou;
}

// ---------------- host ----------------
static inline void gemm_s(cudaStream_t st, const __half* A, const __half* Bt,
                          const float* bias, float* C, __half* aux, __half* aux2,
                          int M, int N, int K, int flags) {
    dim3 g(N / BN, M / BM);
    gemm_tc<<<g, 256, DSMEM, st>>>(A, Bt, bias, C, aux, aux2, M, N, K, flags);
}

extern "C" void kernel_launch(void* const* d_in, const int* in_sizes, int n_in,
                              void* d_out, int out_size) {
    const float* x     = (const float*)d_in[0];
    const int*   ei    = (const int*)  d_in[1];
    const float* w_in  = (const float*)d_in[2];
    const float* b_in  = (const float*)d_in[3];
    const float* ln1_g = (const float*)d_in[4];
    const float* ln1_b = (const float*)d_in[5];
    const float* ln2_g = (const float*)d_in[6];
    const float* ln2_b = (const float*)d_in[7];
    const float* wq = (const float*)d_in[8];  const float* bq = (const float*)d_in[9];
    const float* wk = (const float*)d_in[10]; const float* bk = (const float*)d_in[11];
    const float* wv = (const float*)d_in[12]; const float* bv = (const float*)d_in[13];
    const float* wo = (const float*)d_in[14]; const float* bo = (const float*)d_in[15];
    const float* w1 = (const float*)d_in[16]; const float* b1 = (const float*)d_in[17];
    const float* w2 = (const float*)d_in[18]; const float* b2 = (const float*)d_in[19];
    float* h = (float*)d_out;

    cudaFuncSetAttribute(gemm_tc, cudaFuncAttributeMaxDynamicSharedMemorySize, DSMEM);

    __half *xh, *xnh, *qh, *kh, *vh, *aggh, *ffnh, *winT, *wqkvT, *woT, *w1T, *w2T;
    float *bqkv;
    int *deg, *fill;
    cudaGetSymbolAddress((void**)&xh,    g_xh);
    cudaGetSymbolAddress((void**)&xnh,   g_xnh);
    cudaGetSymbolAddress((void**)&qh,    g_qh);
    cudaGetSymbolAddress((void**)&kh,    g_kh);
    cudaGetSymbolAddress((void**)&vh,    g_vh);
    cudaGetSymbolAddress((void**)&aggh,  g_aggh);
    cudaGetSymbolAddress((void**)&ffnh,  g_ffnh);
    cudaGetSymbolAddress((void**)&winT,  g_winT);
    cudaGetSymbolAddress((void**)&wqkvT, g_wqkvT);
    cudaGetSymbolAddress((void**)&woT,   g_woT);
    cudaGetSymbolAddress((void**)&w1T,   g_w1T);
    cudaGetSymbolAddress((void**)&w2T,   g_w2T);
    cudaGetSymbolAddress((void**)&bqkv,  g_bqkv);
    cudaGetSymbolAddress((void**)&deg,   g_deg);
    cudaGetSymbolAddress((void**)&fill,  g_fill);

    // Streams/events created ONCE (first, non-captured correctness call) and
    // reused every call — resources live in the pre-capture baseline.
    static cudaStream_t sB = nullptr, sC = nullptr;
    static cudaEvent_t ev0 = nullptr, evB = nullptr, evC = nullptr;
    if (sB == nullptr) {
        cudaStreamCreateWithFlags(&sB, cudaStreamNonBlocking);
        cudaStreamCreateWithFlags(&sC, cudaStreamNonBlocking);
        cudaEventCreateWithFlags(&ev0, cudaEventDisableTiming);
        cudaEventCreateWithFlags(&evB, cudaEventDisableTiming);
        cudaEventCreateWithFlags(&evC, cudaEventDisableTiming);
    }

    cudaEventRecord(ev0, 0);
    cudaStreamWaitEvent(sB, ev0, 0);
    cudaStreamWaitEvent(sC, ev0, 0);

    // ---- stream B: CSR build (needed before attn l0) ----
    cudaMemsetAsync(deg,  0, kN * sizeof(int), sB);
    cudaMemsetAsync(fill, 0, kN * sizeof(int), sB);
    deg_count_kernel<<<kE / 256, 256, 0, sB>>>(ei);
    prefix_kernel<<<1, 1024, 0, sB>>>();
    scatter_kernel<<<kE / 256, 256, 0, sB>>>(ei);
    cudaEventRecord(evB, sB);

    // ---- stream C: late-needed weight transposes (before wo-GEMM l0) ----
    {
        dim3 b(32, 8);
        transpose_h<<<dim3(kD / 32, kTD / 32), b, 0, sC>>>(wo, woT, kTD, kD);
        transpose_h<<<dim3(kFFN / 32, kD / 32), b, 0, sC>>>(w1, w1T, kD, kFFN);
        transpose_h<<<dim3(kD / 32, kFFN / 32), b, 0, sC>>>(w2, w2T, kFFN, kD);
        transpose3_h<<<dim3(kTD / 32, kD / 32, 3), b, 0, sC>>>(
            wq + (size_t)kD * kTD, wk + (size_t)kD * kTD, wv + (size_t)kD * kTD,
            wqkvT + (size_t)kQKV * kD, kD, kTD);
        transpose_h<<<dim3(kD / 32, kTD / 32), b, 0, sC>>>(wo + (size_t)kTD * kD,
                                                           woT + (size_t)kD * kTD, kTD, kD);
        transpose_h<<<dim3(kFFN / 32, kD / 32), b, 0, sC>>>(w1 + (size_t)kD * kFFN,
                                                            w1T + (size_t)kFFN * kD, kD, kFFN);
        transpose_h<<<dim3(kD / 32, kFFN / 32), b, 0, sC>>>(w2 + (size_t)kFFN * kD,
                                                            w2T + (size_t)kD * kFFN, kFFN, kD);
        cudaEventRecord(evC, sC);
    }

    // ---- default stream: immediately-needed prep + main chain ----
    {
        dim3 b(32, 8);
        cvt_x<<<kN * kD / 4 / 256, 256>>>(x, xh);
        transpose_h<<<dim3(kD / 32, kD / 32), b>>>(w_in, winT, kD, kD);
        transpose3_h<<<dim3(kTD / 32, kD / 32, 3), b>>>(wq, wk, wv, wqkvT, kD, kTD);
        pack_bias<<<kL * kQKV / 256, 256>>>(bq, bk, bv);
    }

    gemm_s(0, xh, winT, b_in, h, nullptr, nullptr, kN, kD, kD, 0);

    for (int l = 0; l < kL; ++l) {
        ln_kernel<<<kN / 8, 256>>>(h, ln1_g + l * kD, ln1_b + l * kD, xnh);
        gemm_s(0, xnh, wqkvT + (size_t)l * kQKV * kD, bqkv + (size_t)l * kQKV,
               (float*)qh, kh, vh, kN, kQKV, kD, 3);
        if (l == 0) cudaStreamWaitEvent(0, evB, 0);
        attn_kernel<<<kN / 4, 256>>>();
        if (l == 0) cudaStreamWaitEvent(0, evC, 0);
        gemm_s(0, aggh, woT + (size_t)l * kD * kTD, bo + (size_t)l * kD,
               h, nullptr, nullptr, kN, kD, kTD, 1);
        ln_kernel<<<kN / 8, 256>>>(h, ln2_g + l * kD, ln2_b + l * kD, xnh);
        gemm_s(0, xnh, w1T + (size_t)l * kFFN * kD, b1 + (size_t)l * kFFN,
               nullptr, ffnh, nullptr, kN, kFFN, kD, 2);
        gemm_s(0, ffnh, w2T + (size_t)l * kD * kFFN, b2 + (size_t)l * kD,
               h, nullptr, nullptr, kN, kD, kFFN, 1);
    }
}

// round 15
// speedup vs baseline: 1.1320x; 1.1320x over previous
#include <cuda_runtime.h>
#include <cuda_fp16.h>
#include <math.h>
#include <stdint.h>

#define kN   32768
#define kE   (kN * 16)
#define kD   256
#define kH   8
#define kDH  32
#define kTD  256
#define kFFN 1024
#define kL   2
#define kQKV 768

// ---------------- device scratch ----------------
__device__ __half g_xh  [kN * kD];
__device__ __half g_xnh [kN * kD];
__device__ __half g_qh  [kN * kTD];
__device__ __half g_kh  [kN * kTD];
__device__ __half g_vh  [kN * kTD];
__device__ __half g_aggh[kN * kTD];
__device__ __half g_ffnh[kN * kFFN];
__device__ __half g_winT [kD * kD];
__device__ __half g_wqkvT[kL * kQKV * kD];
__device__ __half g_woT  [kL * kD * kTD];
__device__ __half g_w1T  [kL * kFFN * kD];
__device__ __half g_w2T  [kL * kD * kFFN];
__device__ float  g_bqkv [kL * kQKV];
__device__ int    g_deg [kN];
__device__ int    g_fill[kN];
__device__ int    g_off [kN + 1];
__device__ int    g_csr [kE];

// ---------------- helpers ----------------
__device__ __forceinline__ uint32_t smem_u32(const void* p) {
    uint32_t a;
    asm("{ .reg .u64 t; cvta.to.shared.u64 t, %1; cvt.u32.u64 %0, t; }" : "=r"(a) : "l"(p));
    return a;
}
__device__ __forceinline__ void mma_f16(float& d0, float& d1, float& d2, float& d3,
                                        uint32_t a0, uint32_t a1, uint32_t a2, uint32_t a3,
                                        uint32_t b0, uint32_t b1) {
    asm volatile("mma.sync.aligned.m16n8k16.row.col.f32.f16.f16.f32 "
                 "{%0,%1,%2,%3}, {%4,%5,%6,%7}, {%8,%9}, {%0,%1,%2,%3};"
                 : "+f"(d0), "+f"(d1), "+f"(d2), "+f"(d3)
                 : "r"(a0), "r"(a1), "r"(a2), "r"(a3), "r"(b0), "r"(b1));
}
__device__ __forceinline__ void ldsm_x4(uint4& r, uint32_t addr) {
    asm volatile("ldmatrix.sync.aligned.m8n8.x4.shared.b16 {%0,%1,%2,%3}, [%4];"
                 : "=r"(r.x), "=r"(r.y), "=r"(r.z), "=r"(r.w) : "r"(addr));
}
__device__ __forceinline__ void cp16(uint32_t saddr, const void* gaddr) {
    asm volatile("cp.async.cg.shared.global [%0], [%1], 16;" :: "r"(saddr), "l"(gaddr));
}
__device__ __forceinline__ float gelu_exact(float x) {
    return 0.5f * x * (1.f + erff(x * 0.7071067811865475f));
}

// ---------------- fp16 cp.async+ldmatrix GEMM: C = A[M,K] @ Bt[N,K]^T -----
#define BM 128
#define BN 128
#define BK 32
#define ATILE_B (BM * BK * 2)
#define STAGE_B (ATILE_B + BN * BK * 2)
#define NSTAGE 4
#define DSMEM (NSTAGE * STAGE_B)

__global__ void __launch_bounds__(256, 2)
gemm_tc(const __half* __restrict__ A, const __half* __restrict__ Bt,
        const float* __restrict__ bias, float* __restrict__ C,
        __half* __restrict__ aux, __half* __restrict__ aux2,
        int M, int N, int K, int flags) {
    extern __shared__ char dsm[];
    uint32_t sbase = smem_u32(dsm);

    int tid = threadIdx.x;
    int lane = tid & 31;
    int wid = tid >> 5;
    int warp_row = wid >> 2;
    int warp_col = wid & 3;
    int row0 = blockIdx.y * BM, col0 = blockIdx.x * BN;

    const __half* Ag = A + (size_t)row0 * K;
    const __half* Bg = Bt + (size_t)col0 * K;

    int id0 = tid * 2;
    int crow0 = id0 >> 2,       cc0 = id0 & 3;
    int crow1 = (id0 + 1) >> 2, cc1 = (id0 + 1) & 3;
    int cs0 = cc0 ^ ((crow0 >> 1) & 3);
    int cs1 = cc1 ^ ((crow1 >> 1) & 3);
    uint32_t sA0 = crow0 * 64 + cs0 * 16;
    uint32_t sA1 = crow1 * 64 + cs1 * 16;
    size_t gA0 = (size_t)crow0 * K + cc0 * 8;
    size_t gA1 = (size_t)crow1 * K + cc1 * 8;

    int lane_r = lane & 15;
    int lane_c = lane >> 4;
    int xorv = (lane_r >> 1) & 3;

    float acc[4][4][4];
    #pragma unroll
    for (int i = 0; i < 4; ++i)
        #pragma unroll
        for (int j = 0; j < 4; ++j)
            #pragma unroll
            for (int q = 0; q < 4; ++q) acc[i][j][q] = 0.f;

    int nIter = K / BK;

    #pragma unroll
    for (int s = 0; s < 3; ++s) {
        uint32_t Ab = sbase + s * STAGE_B;
        uint32_t Bb = Ab + ATILE_B;
        int kk = s * BK;
        cp16(Ab + sA0, Ag + gA0 + kk);
        cp16(Ab + sA1, Ag + gA1 + kk);
        cp16(Bb + sA0, Bg + gA0 + kk);
        cp16(Bb + sA1, Bg + gA1 + kk);
        asm volatile("cp.async.commit_group;");
    }

    for (int it = 0; it < nIter; ++it) {
        asm volatile("cp.async.wait_group 2;");
        __syncthreads();
        uint32_t Ab = sbase + (it & 3) * STAGE_B;
        uint32_t Bb = Ab + ATILE_B;

        #pragma unroll
        for (int kc = 0; kc < 2; ++kc) {
            uint32_t cs = (uint32_t)(((kc * 2 + lane_c) ^ xorv) * 16);
            uint4 af[4], bm[2];
            #pragma unroll
            for (int mt = 0; mt < 4; ++mt)
                ldsm_x4(af[mt], Ab + (uint32_t)(warp_row * 64 + mt * 16 + lane_r) * 64 + cs);
            #pragma unroll
            for (int ntp = 0; ntp < 2; ++ntp)
                ldsm_x4(bm[ntp], Bb + (uint32_t)(warp_col * 32 + ntp * 16 + lane_r) * 64 + cs);
            #pragma unroll
            for (int mt = 0; mt < 4; ++mt) {
                mma_f16(acc[mt][0][0], acc[mt][0][1], acc[mt][0][2], acc[mt][0][3],
                        af[mt].x, af[mt].y, af[mt].z, af[mt].w, bm[0].x, bm[0].z);
                mma_f16(acc[mt][1][0], acc[mt][1][1], acc[mt][1][2], acc[mt][1][3],
                        af[mt].x, af[mt].y, af[mt].z, af[mt].w, bm[0].y, bm[0].w);
                mma_f16(acc[mt][2][0], acc[mt][2][1], acc[mt][2][2], acc[mt][2][3],
                        af[mt].x, af[mt].y, af[mt].z, af[mt].w, bm[1].x, bm[1].z);
                mma_f16(acc[mt][3][0], acc[mt][3][1], acc[mt][3][2], acc[mt][3][3],
                        af[mt].x, af[mt].y, af[mt].z, af[mt].w, bm[1].y, bm[1].w);
            }
        }
        if (it + 3 < nIter) {
            uint32_t Aw = sbase + ((it + 3) & 3) * STAGE_B;
            uint32_t Bw = Aw + ATILE_B;
            int kk = (it + 3) * BK;
            cp16(Aw + sA0, Ag + gA0 + kk);
            cp16(Aw + sA1, Ag + gA1 + kk);
            cp16(Bw + sA0, Bg + gA0 + kk);
            cp16(Bw + sA1, Bg + gA1 + kk);
        }
        asm volatile("cp.async.commit_group;");
    }

    int g = lane >> 2, tg = lane & 3;
    bool isq = (col0 < 256);
    bool isv = (col0 >= 512);
    #pragma unroll
    for (int mt = 0; mt < 4; ++mt) {
        int rbase = row0 + warp_row * 64 + mt * 16 + g;
        #pragma unroll
        for (int nt = 0; nt < 4; ++nt) {
            int c = col0 + warp_col * 32 + nt * 8 + tg * 2;
            float2 bs = *reinterpret_cast<const float2*>(&bias[c]);
            float v0 = acc[mt][nt][0] + bs.x;
            float v1 = acc[mt][nt][1] + bs.y;
            float v2 = acc[mt][nt][2] + bs.x;
            float v3 = acc[mt][nt][3] + bs.y;
            if (flags == 2) {
                v0 = gelu_exact(v0); v1 = gelu_exact(v1);
                v2 = gelu_exact(v2); v3 = gelu_exact(v3);
                *reinterpret_cast<__half2*>(aux + (size_t)rbase * N + c)       = __floats2half2_rn(v0, v1);
                *reinterpret_cast<__half2*>(aux + (size_t)(rbase + 8) * N + c) = __floats2half2_rn(v2, v3);
            } else if (flags == 3) {
                __half* dst = isq ? reinterpret_cast<__half*>(C) : (isv ? aux2 : aux);
                int cm = c & 255;
                *reinterpret_cast<__half2*>(dst + (size_t)rbase * kTD + cm)       = __floats2half2_rn(v0, v1);
                *reinterpret_cast<__half2*>(dst + (size_t)(rbase + 8) * kTD + cm) = __floats2half2_rn(v2, v3);
            } else {
                float2* cp0 = reinterpret_cast<float2*>(C + (size_t)rbase * N + c);
                float2* cp1 = reinterpret_cast<float2*>(C + (size_t)(rbase + 8) * N + c);
                if (flags == 1) {
                    float2 o0 = *cp0, o1 = *cp1;
                    v0 += o0.x; v1 += o0.y; v2 += o1.x; v3 += o1.y;
                }
                float2 r0 = {v0, v1}, r1 = {v2, v3};
                *cp0 = r0;
                *cp1 = r1;
            }
        }
    }
}

// ---------------- transpose + fp32->fp16 ----------------
__global__ void transpose_h(const float* __restrict__ src, __half* __restrict__ dst,
                            int R, int C) {
    __shared__ float t[32][33];
    int bx = blockIdx.x * 32, by = blockIdx.y * 32;
    int x = bx + threadIdx.x;
    #pragma unroll
    for (int j = 0; j < 32; j += 8)
        t[threadIdx.y + j][threadIdx.x] = src[(size_t)(by + threadIdx.y + j) * C + x];
    __syncthreads();
    int xo = by + threadIdx.x;
    #pragma unroll
    for (int j = 0; j < 32; j += 8)
        dst[(size_t)(bx + threadIdx.y + j) * R + xo] = __float2half_rn(t[threadIdx.x][threadIdx.y + j]);
}
__global__ void transpose3_h(const float* s0, const float* s1, const float* s2,
                             __half* __restrict__ dst, int R, int C) {
    __shared__ float t[32][33];
    const float* src = (blockIdx.z == 0) ? s0 : (blockIdx.z == 1) ? s1 : s2;
    __half* d = dst + (size_t)blockIdx.z * C * R;
    int bx = blockIdx.x * 32, by = blockIdx.y * 32;
    int x = bx + threadIdx.x;
    #pragma unroll
    for (int j = 0; j < 32; j += 8)
        t[threadIdx.y + j][threadIdx.x] = src[(size_t)(by + threadIdx.y + j) * C + x];
    __syncthreads();
    int xo = by + threadIdx.x;
    #pragma unroll
    for (int j = 0; j < 32; j += 8)
        d[(size_t)(bx + threadIdx.y + j) * R + xo] = __float2half_rn(t[threadIdx.x][threadIdx.y + j]);
}

__global__ void cvt_x(const float* __restrict__ x, __half* __restrict__ xh) {
    int i = blockIdx.x * 256 + threadIdx.x;
    float4 v = reinterpret_cast<const float4*>(x)[i];
    __half2 h0 = __floats2half2_rn(v.x, v.y);
    __half2 h1 = __floats2half2_rn(v.z, v.w);
    uint2 u = {*reinterpret_cast<uint32_t*>(&h0), *reinterpret_cast<uint32_t*>(&h1)};
    reinterpret_cast<uint2*>(xh)[i] = u;
}

__global__ void pack_bias(const float* bq, const float* bk, const float* bv) {
    int t = blockIdx.x * 256 + threadIdx.x;
    int l = t / kQKV, r = t % kQKV;
    const float* s = (r < 256) ? bq + l * kTD + r
                   : (r < 512) ? bk + l * kTD + (r - 256)
                               : bv + l * kTD + (r - 512);
    g_bqkv[t] = *s;
}

// ---------------- CSR build ----------------
__global__ void deg_count_kernel(const int* __restrict__ ei) {
    int e = blockIdx.x * 256 + threadIdx.x;
    if (e < kE) atomicAdd(&g_deg[ei[kE + e]], 1);
}
__global__ void prefix_kernel() {
    __shared__ int sums[1024];
    int t = threadIdx.x;
    int base = t * 32;
    int s = 0;
    #pragma unroll 4
    for (int i = 0; i < 32; ++i) s += g_deg[base + i];
    sums[t] = s;
    __syncthreads();
    for (int o = 1; o < 1024; o <<= 1) {
        int v = (t >= o) ? sums[t - o] : 0;
        __syncthreads();
        sums[t] += v;
        __syncthreads();
    }
    int run = sums[t] - s;
    for (int i = 0; i < 32; ++i) { g_off[base + i] = run; run += g_deg[base + i]; }
    if (t == 1023) g_off[kN] = run;
}
__global__ void scatter_kernel(const int* __restrict__ ei) {
    int e = blockIdx.x * 256 + threadIdx.x;
    if (e < kE) {
        int d = ei[kE + e];
        int pos = g_off[d] + atomicAdd(&g_fill[d], 1);
        g_csr[pos] = ei[e];
    }
}

// ---------------- LayerNorm: warp per row, fp32 in, fp16 out --------------
__global__ void __launch_bounds__(256)
ln_kernel(const float* __restrict__ x, const float* __restrict__ gg,
          const float* __restrict__ bb, __half* __restrict__ y) {
    int lane = threadIdx.x & 31;
    int row = blockIdx.x * 8 + (threadIdx.x >> 5);
    const float4* xr = reinterpret_cast<const float4*>(x + (size_t)row * kD);
    float4 a0 = xr[lane];
    float4 a1 = xr[lane + 32];
    float s = a0.x + a0.y + a0.z + a0.w + a1.x + a1.y + a1.z + a1.w;
    float q = a0.x*a0.x + a0.y*a0.y + a0.z*a0.z + a0.w*a0.w
            + a1.x*a1.x + a1.y*a1.y + a1.z*a1.z + a1.w*a1.w;
    #pragma unroll
    for (int o = 16; o; o >>= 1) {
        s += __shfl_xor_sync(~0u, s, o);
        q += __shfl_xor_sync(~0u, q, o);
    }
    float mean = s * (1.f / kD);
    float var = q * (1.f / kD) - mean * mean;
    float inv = rsqrtf(var + 1e-5f);
    float4 g0 = reinterpret_cast<const float4*>(gg)[lane];
    float4 g1 = reinterpret_cast<const float4*>(gg)[lane + 32];
    float4 b0 = reinterpret_cast<const float4*>(bb)[lane];
    float4 b1 = reinterpret_cast<const float4*>(bb)[lane + 32];
    __half2 o0 = __floats2half2_rn((a0.x - mean) * inv * g0.x + b0.x, (a0.y - mean) * inv * g0.y + b0.y);
    __half2 o1 = __floats2half2_rn((a0.z - mean) * inv * g0.z + b0.z, (a0.w - mean) * inv * g0.w + b0.w);
    __half2 o2 = __floats2half2_rn((a1.x - mean) * inv * g1.x + b1.x, (a1.y - mean) * inv * g1.y + b1.y);
    __half2 o3 = __floats2half2_rn((a1.z - mean) * inv * g1.z + b1.z, (a1.w - mean) * inv * g1.w + b1.w);
    uint2 u0 = {*reinterpret_cast<uint32_t*>(&o0), *reinterpret_cast<uint32_t*>(&o1)};
    uint2 u1 = {*reinterpret_cast<uint32_t*>(&o2), *reinterpret_cast<uint32_t*>(&o3)};
    *reinterpret_cast<uint2*>(y + (size_t)row * kD + lane * 4)       = u0;
    *reinterpret_cast<uint2*>(y + (size_t)row * kD + 128 + lane * 4) = u1;
}

// ------- Edge attention: warp = 4 heads, lane = 4 dims, 3-shfl reduce -----
__global__ void __launch_bounds__(256)
attn_kernel() {
    int tid = threadIdx.x;
    int lane = tid & 31;
    int wid = tid >> 5;
    int node = blockIdx.x * 4 + (wid >> 1);
    int head = ((wid & 1) << 2) + (lane >> 3);
    int d0 = (lane & 7) << 2;
    int base = node * kTD + head * kDH + d0;

    int beg = g_off[node], end = g_off[node + 1];
    uint2* outp = reinterpret_cast<uint2*>(g_aggh + base);
    if (beg == end) { uint2 z = {0u, 0u}; *outp = z; return; }

    uint2 qu = *reinterpret_cast<const uint2*>(g_qh + base);
    float2 qa = __half22float2(*reinterpret_cast<const __half2*>(&qu.x));
    float2 qb = __half22float2(*reinterpret_cast<const __half2*>(&qu.y));
    const float sc = 0.17677669529663687f;
    float q0 = qa.x * sc, q1 = qa.y * sc, q2 = qb.x * sc, q3 = qb.y * sc;

    float l = 0.f, a0 = 0.f, a1 = 0.f, a2 = 0.f, a3 = 0.f;
    int hoff = head * kDH + d0;

    {
        uint2 ku = *reinterpret_cast<const uint2*>(g_kh + base);
        uint2 vu = *reinterpret_cast<const uint2*>(g_vh + base);
        float2 ka = __half22float2(*reinterpret_cast<const __half2*>(&ku.x));
        float2 kb = __half22float2(*reinterpret_cast<const __half2*>(&ku.y));
        float s = q0 * ka.x + q1 * ka.y + q2 * kb.x + q3 * kb.y;
        s += __shfl_xor_sync(~0u, s, 4);
        s += __shfl_xor_sync(~0u, s, 2);
        s += __shfl_xor_sync(~0u, s, 1);
        float p = __expf(s);
        float2 va = __half22float2(*reinterpret_cast<const __half2*>(&vu.x));
        float2 vb = __half22float2(*reinterpret_cast<const __half2*>(&vu.y));
        l += p; a0 += p * va.x; a1 += p * va.y; a2 += p * vb.x; a3 += p * vb.y;
    }
    int i = beg;
    for (; i + 1 < end; i += 2) {
        int s0 = g_csr[i], s1 = g_csr[i + 1];
        const __half* k0p = g_kh + (size_t)s0 * kTD + hoff;
        const __half* k1p = g_kh + (size_t)s1 * kTD + hoff;
        const __half* v0p = g_vh + (size_t)s0 * kTD + hoff;
        const __half* v1p = g_vh + (size_t)s1 * kTD + hoff;
        uint2 k0u = *reinterpret_cast<const uint2*>(k0p);
        uint2 k1u = *reinterpret_cast<const uint2*>(k1p);
        uint2 v0u = *reinterpret_cast<const uint2*>(v0p);
        uint2 v1u = *reinterpret_cast<const uint2*>(v1p);
        float2 k0a = __half22float2(*reinterpret_cast<const __half2*>(&k0u.x));
        float2 k0b = __half22float2(*reinterpret_cast<const __half2*>(&k0u.y));
        float2 k1a = __half22float2(*reinterpret_cast<const __half2*>(&k1u.x));
        float2 k1b = __half22float2(*reinterpret_cast<const __half2*>(&k1u.y));
        float sa = q0 * k0a.x + q1 * k0a.y + q2 * k0b.x + q3 * k0b.y;
        float sb = q0 * k1a.x + q1 * k1a.y + q2 * k1b.x + q3 * k1b.y;
        sa += __shfl_xor_sync(~0u, sa, 4); sb += __shfl_xor_sync(~0u, sb, 4);
        sa += __shfl_xor_sync(~0u, sa, 2); sb += __shfl_xor_sync(~0u, sb, 2);
        sa += __shfl_xor_sync(~0u, sa, 1); sb += __shfl_xor_sync(~0u, sb, 1);
        float p0 = __expf(sa), p1 = __expf(sb);
        float2 v0a = __half22float2(*reinterpret_cast<const __half2*>(&v0u.x));
        float2 v0b = __half22float2(*reinterpret_cast<const __half2*>(&v0u.y));
        float2 v1a = __half22float2(*reinterpret_cast<const __half2*>(&v1u.x));
        float2 v1b = __half22float2(*reinterpret_cast<const __half2*>(&v1u.y));
        l += p0 + p1;
        a0 += p0 * v0a.x + p1 * v1a.x;
        a1 += p0 * v0a.y + p1 * v1a.y;
        a2 += p0 * v0b.x + p1 * v1b.x;
        a3 += p0 * v0b.y + p1 * v1b.y;
    }
    if (i < end) {
        int s0 = g_csr[i];
        const __half* kp = g_kh + (size_t)s0 * kTD + hoff;
        const __half* vp = g_vh + (size_t)s0 * kTD + hoff;
        uint2 ku = *reinterpret_cast<const uint2*>(kp);
        uint2 vu = *reinterpret_cast<const uint2*>(vp);
        float2 ka = __half22float2(*reinterpret_cast<const __half2*>(&ku.x));
        float2 kb = __half22float2(*reinterpret_cast<const __half2*>(&ku.y));
        float s = q0 * ka.x + q1 * ka.y + q2 * kb.x + q3 * kb.y;
        s += __shfl_xor_sync(~0u, s, 4);
        s += __shfl_xor_sync(~0u, s, 2);
        s += __shfl_xor_sync(~0u, s, 1);
        float p = __expf(s);
        float2 va = __half22float2(*reinterpret_cast<const __half2*>(&vu.x));
        float2 vb = __half22float2(*reinterpret_cast<const __half2*>(&vu.y));
        l += p; a0 += p * va.x; a1 += p * va.y; a2 += p * vb.x; a3 += p * vb.y;
    }
    float inv = 1.f / l;
    __half2 o0 = __floats2half2_rn(a0 * inv, a1 * inv);
    __half2 o1 = __floats2half2_rn(a2 * inv, a3 * inv);
    uint2 ou = {*reinterpret_cast<uint32_t*>(&o0), *reinterpret_cast<uint32_t*>(&o1)};
    *outp = ou;
}

// ---------------- host ----------------
static inline void gemm_s(cudaStream_t st, const __half* A, const __half* Bt,
                          const float* bias, float* C, __half* aux, __half* aux2,
                          int M, int N, int K, int flags) {
    dim3 g(N / BN, M / BM);
    gemm_tc<<<g, 256, DSMEM, st>>>(A, Bt, bias, C, aux, aux2, M, N, K, flags);
}

extern "C" void kernel_launch(void* const* d_in, const int* in_sizes, int n_in,
                              void* d_out, int out_size) {
    const float* x     = (const float*)d_in[0];
    const int*   ei    = (const int*)  d_in[1];
    const float* w_in  = (const float*)d_in[2];
    const float* b_in  = (const float*)d_in[3];
    const float* ln1_g = (const float*)d_in[4];
    const float* ln1_b = (const float*)d_in[5];
    const float* ln2_g = (const float*)d_in[6];
    const float* ln2_b = (const float*)d_in[7];
    const float* wq = (const float*)d_in[8];  const float* bq = (const float*)d_in[9];
    const float* wk = (const float*)d_in[10]; const float* bk = (const float*)d_in[11];
    const float* wv = (const float*)d_in[12]; const float* bv = (const float*)d_in[13];
    const float* wo = (const float*)d_in[14]; const float* bo = (const float*)d_in[15];
    const float* w1 = (const float*)d_in[16]; const float* b1 = (const float*)d_in[17];
    const float* w2 = (const float*)d_in[18]; const float* b2 = (const float*)d_in[19];
    float* h = (float*)d_out;

    cudaFuncSetAttribute(gemm_tc, cudaFuncAttributeMaxDynamicSharedMemorySize, DSMEM);

    __half *xh, *xnh, *qh, *kh, *vh, *aggh, *ffnh, *winT, *wqkvT, *woT, *w1T, *w2T;
    float *bqkv;
    int *deg, *fill;
    cudaGetSymbolAddress((void**)&xh,    g_xh);
    cudaGetSymbolAddress((void**)&xnh,   g_xnh);
    cudaGetSymbolAddress((void**)&qh,    g_qh);
    cudaGetSymbolAddress((void**)&kh,    g_kh);
    cudaGetSymbolAddress((void**)&vh,    g_vh);
    cudaGetSymbolAddress((void**)&aggh,  g_aggh);
    cudaGetSymbolAddress((void**)&ffnh,  g_ffnh);
    cudaGetSymbolAddress((void**)&winT,  g_winT);
    cudaGetSymbolAddress((void**)&wqkvT, g_wqkvT);
    cudaGetSymbolAddress((void**)&woT,   g_woT);
    cudaGetSymbolAddress((void**)&w1T,   g_w1T);
    cudaGetSymbolAddress((void**)&w2T,   g_w2T);
    cudaGetSymbolAddress((void**)&bqkv,  g_bqkv);
    cudaGetSymbolAddress((void**)&deg,   g_deg);
    cudaGetSymbolAddress((void**)&fill,  g_fill);

    // Streams/events created ONCE (first, non-captured correctness call) and
    // reused every call — resources live in the pre-capture baseline.
    static cudaStream_t sB = nullptr, sC = nullptr;
    static cudaEvent_t ev0 = nullptr, evB = nullptr, evC1 = nullptr, evC2 = nullptr, evW = nullptr;
    if (sB == nullptr) {
        cudaStreamCreateWithFlags(&sB, cudaStreamNonBlocking);
        cudaStreamCreateWithFlags(&sC, cudaStreamNonBlocking);
        cudaEventCreateWithFlags(&ev0, cudaEventDisableTiming);
        cudaEventCreateWithFlags(&evB, cudaEventDisableTiming);
        cudaEventCreateWithFlags(&evC1, cudaEventDisableTiming);
        cudaEventCreateWithFlags(&evC2, cudaEventDisableTiming);
        cudaEventCreateWithFlags(&evW, cudaEventDisableTiming);
    }

    cudaEventRecord(ev0, 0);
    cudaStreamWaitEvent(sB, ev0, 0);
    cudaStreamWaitEvent(sC, ev0, 0);

    // ---- stream B: winT (needed by input proj) then CSR build ----
    {
        dim3 b(32, 8);
        transpose_h<<<dim3(kD / 32, kD / 32), b, 0, sB>>>(w_in, winT, kD, kD);
        cudaEventRecord(evW, sB);
    }
    cudaMemsetAsync(deg,  0, kN * sizeof(int), sB);
    cudaMemsetAsync(fill, 0, kN * sizeof(int), sB);
    deg_count_kernel<<<kE / 256, 256, 0, sB>>>(ei);
    prefix_kernel<<<1, 1024, 0, sB>>>();
    scatter_kernel<<<kE / 256, 256, 0, sB>>>(ei);
    cudaEventRecord(evB, sB);

    // ---- stream C: qkvT(l0)+bias first (needed by qkv l0), then the rest --
    {
        dim3 b(32, 8);
        transpose3_h<<<dim3(kTD / 32, kD / 32, 3), b, 0, sC>>>(wq, wk, wv, wqkvT, kD, kTD);
        pack_bias<<<kL * kQKV / 256, 256, 0, sC>>>(bq, bk, bv);
        cudaEventRecord(evC1, sC);
        transpose_h<<<dim3(kD / 32, kTD / 32), b, 0, sC>>>(wo, woT, kTD, kD);
        transpose_h<<<dim3(kFFN / 32, kD / 32), b, 0, sC>>>(w1, w1T, kD, kFFN);
        transpose_h<<<dim3(kD / 32, kFFN / 32), b, 0, sC>>>(w2, w2T, kFFN, kD);
        transpose3_h<<<dim3(kTD / 32, kD / 32, 3), b, 0, sC>>>(
            wq + (size_t)kD * kTD, wk + (size_t)kD * kTD, wv + (size_t)kD * kTD,
            wqkvT + (size_t)kQKV * kD, kD, kTD);
        transpose_h<<<dim3(kD / 32, kTD / 32), b, 0, sC>>>(wo + (size_t)kTD * kD,
                                                           woT + (size_t)kD * kTD, kTD, kD);
        transpose_h<<<dim3(kFFN / 32, kD / 32), b, 0, sC>>>(w1 + (size_t)kD * kFFN,
                                                            w1T + (size_t)kFFN * kD, kD, kFFN);
        transpose_h<<<dim3(kD / 32, kFFN / 32), b, 0, sC>>>(w2 + (size_t)kFFN * kD,
                                                            w2T + (size_t)kD * kFFN, kFFN, kD);
        cudaEventRecord(evC2, sC);
    }

    // ---- default stream: cvt_x only, then the main chain ----
    cvt_x<<<kN * kD / 4 / 256, 256>>>(x, xh);
    cudaStreamWaitEvent(0, evW, 0);
    gemm_s(0, xh, winT, b_in, h, nullptr, nullptr, kN, kD, kD, 0);

    for (int l = 0; l < kL; ++l) {
        ln_kernel<<<kN / 8, 256>>>(h, ln1_g + l * kD, ln1_b + l * kD, xnh);
        if (l == 0) cudaStreamWaitEvent(0, evC1, 0);
        gemm_s(0, xnh, wqkvT + (size_t)l * kQKV * kD, bqkv + (size_t)l * kQKV,
               (float*)qh, kh, vh, kN, kQKV, kD, 3);
        if (l == 0) cudaStreamWaitEvent(0, evB, 0);
        attn_kernel<<<kN / 4, 256>>>();
        if (l == 0) cudaStreamWaitEvent(0, evC2, 0);
        gemm_s(0, aggh, woT + (size_t)l * kD * kTD, bo + (size_t)l * kD,
               h, nullptr, nullptr, kN, kD, kTD, 1);
        ln_kernel<<<kN / 8, 256>>>(h, ln2_g + l * kD, ln2_b + l * kD, xnh);
        gemm_s(0, xnh, w1T + (size_t)l * kFFN * kD, b1 + (size_t)l * kFFN,
               nullptr, ffnh, nullptr, kN, kFFN, kD, 2);
        gemm_s(0, ffnh, w2T + (size_t)l * kD * kFFN, b2 + (size_t)l * kD,
               h, nullptr, nullptr, kN, kD, kFFN, 1);
    }
}

// round 16
// speedup vs baseline: 1.1666x; 1.0306x over previous
#include <cuda_runtime.h>
#include <cuda_fp16.h>
#include <math.h>
#include <stdint.h>

#define kN   32768
#define kE   (kN * 16)
#define kD   256
#define kH   8
#define kDH  32
#define kTD  256
#define kFFN 1024
#define kL   2
#define kQKV 768

// ---------------- device scratch ----------------
__device__ __half g_xnh [kN * kD];
__device__ __half g_qh  [kN * kTD];
__device__ __half g_kh  [kN * kTD];
__device__ __half g_vh  [kN * kTD];
__device__ __half g_aggh[kN * kTD];
__device__ __half g_ffnh[kN * kFFN];
__device__ __half g_winT [kD * kD];
__device__ __half g_wqkvT[kL * kQKV * kD];
__device__ __half g_woT  [kL * kD * kTD];
__device__ __half g_w1T  [kL * kFFN * kD];
__device__ __half g_w2T  [kL * kD * kFFN];
__device__ float  g_bqkv [kL * kQKV];
__device__ int    g_deg [kN];
__device__ int    g_fill[kN];
__device__ int    g_off [kN + 1];
__device__ int    g_csr [kE];

// ---------------- helpers ----------------
__device__ __forceinline__ uint32_t smem_u32(const void* p) {
    uint32_t a;
    asm("{ .reg .u64 t; cvta.to.shared.u64 t, %1; cvt.u32.u64 %0, t; }" : "=r"(a) : "l"(p));
    return a;
}
__device__ __forceinline__ void mma_f16(float& d0, float& d1, float& d2, float& d3,
                                        uint32_t a0, uint32_t a1, uint32_t a2, uint32_t a3,
                                        uint32_t b0, uint32_t b1) {
    asm volatile("mma.sync.aligned.m16n8k16.row.col.f32.f16.f16.f32 "
                 "{%0,%1,%2,%3}, {%4,%5,%6,%7}, {%8,%9}, {%0,%1,%2,%3};"
                 : "+f"(d0), "+f"(d1), "+f"(d2), "+f"(d3)
                 : "r"(a0), "r"(a1), "r"(a2), "r"(a3), "r"(b0), "r"(b1));
}
__device__ __forceinline__ void ldsm_x4(uint4& r, uint32_t addr) {
    asm volatile("ldmatrix.sync.aligned.m8n8.x4.shared.b16 {%0,%1,%2,%3}, [%4];"
                 : "=r"(r.x), "=r"(r.y), "=r"(r.z), "=r"(r.w) : "r"(addr));
}
__device__ __forceinline__ void cp16(uint32_t saddr, const void* gaddr) {
    asm volatile("cp.async.cg.shared.global [%0], [%1], 16;" :: "r"(saddr), "l"(gaddr));
}
__device__ __forceinline__ void sts16(uint32_t saddr, uint32_t a, uint32_t b, uint32_t c, uint32_t d) {
    asm volatile("st.shared.v4.b32 [%0], {%1,%2,%3,%4};" :: "r"(saddr), "r"(a), "r"(b), "r"(c), "r"(d) : "memory");
}
__device__ __forceinline__ uint32_t pack_h2f(float lo, float hi) {
    __half2 h = __floats2half2_rn(lo, hi);
    return *reinterpret_cast<uint32_t*>(&h);
}
__device__ __forceinline__ float gelu_exact(float x) {
    return 0.5f * x * (1.f + erff(x * 0.7071067811865475f));
}

// ---------------- fp16 cp.async+ldmatrix GEMM: C = A[M,K] @ Bt[N,K]^T -----
// AF32: A operand is fp32 in gmem (converted inline while staging).
#define BM 128
#define BN 128
#define BK 32
#define ATILE_B (BM * BK * 2)
#define STAGE_B (ATILE_B + BN * BK * 2)
#define NSTAGE 4
#define DSMEM (NSTAGE * STAGE_B)

template <int AF32>
__global__ void __launch_bounds__(256, 2)
gemm_tc(const void* __restrict__ Av, const __half* __restrict__ Bt,
        const float* __restrict__ bias, float* __restrict__ C,
        __half* __restrict__ aux, __half* __restrict__ aux2,
        int M, int N, int K, int flags) {
    extern __shared__ char dsm[];
    uint32_t sbase = smem_u32(dsm);

    int tid = threadIdx.x;
    int lane = tid & 31;
    int wid = tid >> 5;
    int warp_row = wid >> 2;
    int warp_col = wid & 3;
    int row0 = blockIdx.y * BM, col0 = blockIdx.x * BN;

    const __half* Agh = (const __half*)Av + (size_t)row0 * K;
    const float*  Agf = (const float*)Av + (size_t)row0 * K;
    const __half* Bg  = Bt + (size_t)col0 * K;

    int id0 = tid * 2;
    int crow0 = id0 >> 2,       cc0 = id0 & 3;
    int crow1 = (id0 + 1) >> 2, cc1 = (id0 + 1) & 3;
    int cs0 = cc0 ^ ((crow0 >> 1) & 3);
    int cs1 = cc1 ^ ((crow1 >> 1) & 3);
    uint32_t sA0 = crow0 * 64 + cs0 * 16;
    uint32_t sA1 = crow1 * 64 + cs1 * 16;
    size_t gA0 = (size_t)crow0 * K + cc0 * 8;
    size_t gA1 = (size_t)crow1 * K + cc1 * 8;

    int lane_r = lane & 15;
    int lane_c = lane >> 4;
    int xorv = (lane_r >> 1) & 3;

    float acc[4][4][4];
    #pragma unroll
    for (int i = 0; i < 4; ++i)
        #pragma unroll
        for (int j = 0; j < 4; ++j)
            #pragma unroll
            for (int q = 0; q < 4; ++q) acc[i][j][q] = 0.f;

    int nIter = K / BK;
    float4 pf[4];   // AF32 register prefetch

    #pragma unroll
    for (int s = 0; s < 3; ++s) {
        uint32_t Ab = sbase + s * STAGE_B;
        uint32_t Bb = Ab + ATILE_B;
        int kk = s * BK;
        if (AF32) {
            float4 u0 = *reinterpret_cast<const float4*>(Agf + gA0 + kk);
            float4 u1 = *reinterpret_cast<const float4*>(Agf + gA0 + kk + 4);
            float4 u2 = *reinterpret_cast<const float4*>(Agf + gA1 + kk);
            float4 u3 = *reinterpret_cast<const float4*>(Agf + gA1 + kk + 4);
            sts16(Ab + sA0, pack_h2f(u0.x, u0.y), pack_h2f(u0.z, u0.w),
                             pack_h2f(u1.x, u1.y), pack_h2f(u1.z, u1.w));
            sts16(Ab + sA1, pack_h2f(u2.x, u2.y), pack_h2f(u2.z, u2.w),
                             pack_h2f(u3.x, u3.y), pack_h2f(u3.z, u3.w));
        } else {
            cp16(Ab + sA0, Agh + gA0 + kk);
            cp16(Ab + sA1, Agh + gA1 + kk);
        }
        cp16(Bb + sA0, Bg + gA0 + kk);
        cp16(Bb + sA1, Bg + gA1 + kk);
        asm volatile("cp.async.commit_group;");
    }

    for (int it = 0; it < nIter; ++it) {
        bool more = (it + 3 < nIter);
        if (AF32 && more) {
            int kk = (it + 3) * BK;
            pf[0] = *reinterpret_cast<const float4*>(Agf + gA0 + kk);
            pf[1] = *reinterpret_cast<const float4*>(Agf + gA0 + kk + 4);
            pf[2] = *reinterpret_cast<const float4*>(Agf + gA1 + kk);
            pf[3] = *reinterpret_cast<const float4*>(Agf + gA1 + kk + 4);
        }
        asm volatile("cp.async.wait_group 2;");
        __syncthreads();
        uint32_t Ab = sbase + (it & 3) * STAGE_B;
        uint32_t Bb = Ab + ATILE_B;

        #pragma unroll
        for (int kc = 0; kc < 2; ++kc) {
            uint32_t cs = (uint32_t)(((kc * 2 + lane_c) ^ xorv) * 16);
            uint4 af[4], bm[2];
            #pragma unroll
            for (int mt = 0; mt < 4; ++mt)
                ldsm_x4(af[mt], Ab + (uint32_t)(warp_row * 64 + mt * 16 + lane_r) * 64 + cs);
            #pragma unroll
            for (int ntp = 0; ntp < 2; ++ntp)
                ldsm_x4(bm[ntp], Bb + (uint32_t)(warp_col * 32 + ntp * 16 + lane_r) * 64 + cs);
            #pragma unroll
            for (int mt = 0; mt < 4; ++mt) {
                mma_f16(acc[mt][0][0], acc[mt][0][1], acc[mt][0][2], acc[mt][0][3],
                        af[mt].x, af[mt].y, af[mt].z, af[mt].w, bm[0].x, bm[0].z);
                mma_f16(acc[mt][1][0], acc[mt][1][1], acc[mt][1][2], acc[mt][1][3],
                        af[mt].x, af[mt].y, af[mt].z, af[mt].w, bm[0].y, bm[0].w);
                mma_f16(acc[mt][2][0], acc[mt][2][1], acc[mt][2][2], acc[mt][2][3],
                        af[mt].x, af[mt].y, af[mt].z, af[mt].w, bm[1].x, bm[1].z);
                mma_f16(acc[mt][3][0], acc[mt][3][1], acc[mt][3][2], acc[mt][3][3],
                        af[mt].x, af[mt].y, af[mt].z, af[mt].w, bm[1].y, bm[1].w);
            }
        }
        if (more) {
            uint32_t Aw = sbase + ((it + 3) & 3) * STAGE_B;
            uint32_t Bw = Aw + ATILE_B;
            int kk = (it + 3) * BK;
            if (AF32) {
                sts16(Aw + sA0, pack_h2f(pf[0].x, pf[0].y), pack_h2f(pf[0].z, pf[0].w),
                                 pack_h2f(pf[1].x, pf[1].y), pack_h2f(pf[1].z, pf[1].w));
                sts16(Aw + sA1, pack_h2f(pf[2].x, pf[2].y), pack_h2f(pf[2].z, pf[2].w),
                                 pack_h2f(pf[3].x, pf[3].y), pack_h2f(pf[3].z, pf[3].w));
            } else {
                cp16(Aw + sA0, Agh + gA0 + kk);
                cp16(Aw + sA1, Agh + gA1 + kk);
            }
            cp16(Bw + sA0, Bg + gA0 + kk);
            cp16(Bw + sA1, Bg + gA1 + kk);
        }
        asm volatile("cp.async.commit_group;");
    }

    int g = lane >> 2, tg = lane & 3;
    bool isq = (col0 < 256);
    bool isv = (col0 >= 512);
    #pragma unroll
    for (int mt = 0; mt < 4; ++mt) {
        int rbase = row0 + warp_row * 64 + mt * 16 + g;
        #pragma unroll
        for (int nt = 0; nt < 4; ++nt) {
            int c = col0 + warp_col * 32 + nt * 8 + tg * 2;
            float2 bs = *reinterpret_cast<const float2*>(&bias[c]);
            float v0 = acc[mt][nt][0] + bs.x;
            float v1 = acc[mt][nt][1] + bs.y;
            float v2 = acc[mt][nt][2] + bs.x;
            float v3 = acc[mt][nt][3] + bs.y;
            if (flags == 2) {
                v0 = gelu_exact(v0); v1 = gelu_exact(v1);
                v2 = gelu_exact(v2); v3 = gelu_exact(v3);
                *reinterpret_cast<__half2*>(aux + (size_t)rbase * N + c)       = __floats2half2_rn(v0, v1);
                *reinterpret_cast<__half2*>(aux + (size_t)(rbase + 8) * N + c) = __floats2half2_rn(v2, v3);
            } else if (flags == 3) {
                __half* dst = isq ? reinterpret_cast<__half*>(C) : (isv ? aux2 : aux);
                int cm = c & 255;
                *reinterpret_cast<__half2*>(dst + (size_t)rbase * kTD + cm)       = __floats2half2_rn(v0, v1);
                *reinterpret_cast<__half2*>(dst + (size_t)(rbase + 8) * kTD + cm) = __floats2half2_rn(v2, v3);
            } else {
                float2* cp0 = reinterpret_cast<float2*>(C + (size_t)rbase * N + c);
                float2* cp1 = reinterpret_cast<float2*>(C + (size_t)(rbase + 8) * N + c);
                if (flags == 1) {
                    float2 o0 = *cp0, o1 = *cp1;
                    v0 += o0.x; v1 += o0.y; v2 += o1.x; v3 += o1.y;
                }
                float2 r0 = {v0, v1}, r1 = {v2, v3};
                *cp0 = r0;
                *cp1 = r1;
            }
        }
    }
}

// ---------------- transpose + fp32->fp16 ----------------
__global__ void transpose_h(const float* __restrict__ src, __half* __restrict__ dst,
                            int R, int C) {
    __shared__ float t[32][33];
    int bx = blockIdx.x * 32, by = blockIdx.y * 32;
    int x = bx + threadIdx.x;
    #pragma unroll
    for (int j = 0; j < 32; j += 8)
        t[threadIdx.y + j][threadIdx.x] = src[(size_t)(by + threadIdx.y + j) * C + x];
    __syncthreads();
    int xo = by + threadIdx.x;
    #pragma unroll
    for (int j = 0; j < 32; j += 8)
        dst[(size_t)(bx + threadIdx.y + j) * R + xo] = __float2half_rn(t[threadIdx.x][threadIdx.y + j]);
}
__global__ void transpose3_h(const float* s0, const float* s1, const float* s2,
                             __half* __restrict__ dst, int R, int C) {
    __shared__ float t[32][33];
    const float* src = (blockIdx.z == 0) ? s0 : (blockIdx.z == 1) ? s1 : s2;
    __half* d = dst + (size_t)blockIdx.z * C * R;
    int bx = blockIdx.x * 32, by = blockIdx.y * 32;
    int x = bx + threadIdx.x;
    #pragma unroll
    for (int j = 0; j < 32; j += 8)
        t[threadIdx.y + j][threadIdx.x] = src[(size_t)(by + threadIdx.y + j) * C + x];
    __syncthreads();
    int xo = by + threadIdx.x;
    #pragma unroll
    for (int j = 0; j < 32; j += 8)
        d[(size_t)(bx + threadIdx.y + j) * R + xo] = __float2half_rn(t[threadIdx.x][threadIdx.y + j]);
}

__global__ void pack_bias(const float* bq, const float* bk, const float* bv) {
    int t = blockIdx.x * 256 + threadIdx.x;
    int l = t / kQKV, r = t % kQKV;
    const float* s = (r < 256) ? bq + l * kTD + r
                   : (r < 512) ? bk + l * kTD + (r - 256)
                               : bv + l * kTD + (r - 512);
    g_bqkv[t] = *s;
}

// ---------------- CSR build ----------------
__global__ void deg_count_kernel(const int* __restrict__ ei) {
    int e = blockIdx.x * 256 + threadIdx.x;
    if (e < kE) atomicAdd(&g_deg[ei[kE + e]], 1);
}
__global__ void prefix_kernel() {
    __shared__ int sums[1024];
    int t = threadIdx.x;
    int base = t * 32;
    int s = 0;
    #pragma unroll 4
    for (int i = 0; i < 32; ++i) s += g_deg[base + i];
    sums[t] = s;
    __syncthreads();
    for (int o = 1; o < 1024; o <<= 1) {
        int v = (t >= o) ? sums[t - o] : 0;
        __syncthreads();
        sums[t] += v;
        __syncthreads();
    }
    int run = sums[t] - s;
    for (int i = 0; i < 32; ++i) { g_off[base + i] = run; run += g_deg[base + i]; }
    if (t == 1023) g_off[kN] = run;
}
__global__ void scatter_kernel(const int* __restrict__ ei) {
    int e = blockIdx.x * 256 + threadIdx.x;
    if (e < kE) {
        int d = ei[kE + e];
        int pos = g_off[d] + atomicAdd(&g_fill[d], 1);
        g_csr[pos] = ei[e];
    }
}

// ---------------- LayerNorm: warp per row, fp32 in, fp16 out --------------
__global__ void __launch_bounds__(256)
ln_kernel(const float* __restrict__ x, const float* __restrict__ gg,
          const float* __restrict__ bb, __half* __restrict__ y) {
    int lane = threadIdx.x & 31;
    int row = blockIdx.x * 8 + (threadIdx.x >> 5);
    const float4* xr = reinterpret_cast<const float4*>(x + (size_t)row * kD);
    float4 a0 = xr[lane];
    float4 a1 = xr[lane + 32];
    float s = a0.x + a0.y + a0.z + a0.w + a1.x + a1.y + a1.z + a1.w;
    float q = a0.x*a0.x + a0.y*a0.y + a0.z*a0.z + a0.w*a0.w
            + a1.x*a1.x + a1.y*a1.y + a1.z*a1.z + a1.w*a1.w;
    #pragma unroll
    for (int o = 16; o; o >>= 1) {
        s += __shfl_xor_sync(~0u, s, o);
        q += __shfl_xor_sync(~0u, q, o);
    }
    float mean = s * (1.f / kD);
    float var = q * (1.f / kD) - mean * mean;
    float inv = rsqrtf(var + 1e-5f);
    float4 g0 = reinterpret_cast<const float4*>(gg)[lane];
    float4 g1 = reinterpret_cast<const float4*>(gg)[lane + 32];
    float4 b0 = reinterpret_cast<const float4*>(bb)[lane];
    float4 b1 = reinterpret_cast<const float4*>(bb)[lane + 32];
    __half2 o0 = __floats2half2_rn((a0.x - mean) * inv * g0.x + b0.x, (a0.y - mean) * inv * g0.y + b0.y);
    __half2 o1 = __floats2half2_rn((a0.z - mean) * inv * g0.z + b0.z, (a0.w - mean) * inv * g0.w + b0.w);
    __half2 o2 = __floats2half2_rn((a1.x - mean) * inv * g1.x + b1.x, (a1.y - mean) * inv * g1.y + b1.y);
    __half2 o3 = __floats2half2_rn((a1.z - mean) * inv * g1.z + b1.z, (a1.w - mean) * inv * g1.w + b1.w);
    uint2 u0 = {*reinterpret_cast<uint32_t*>(&o0), *reinterpret_cast<uint32_t*>(&o1)};
    uint2 u1 = {*reinterpret_cast<uint32_t*>(&o2), *reinterpret_cast<uint32_t*>(&o3)};
    *reinterpret_cast<uint2*>(y + (size_t)row * kD + lane * 4)       = u0;
    *reinterpret_cast<uint2*>(y + (size_t)row * kD + 128 + lane * 4) = u1;
}

// ------- Edge attention: warp = 4 heads, lane = 4 dims, 3-shfl reduce -----
__global__ void __launch_bounds__(256)
attn_kernel() {
    int tid = threadIdx.x;
    int lane = tid & 31;
    int wid = tid >> 5;
    int node = blockIdx.x * 4 + (wid >> 1);
    int head = ((wid & 1) << 2) + (lane >> 3);
    int d0 = (lane & 7) << 2;
    int base = node * kTD + head * kDH + d0;

    int beg = g_off[node], end = g_off[node + 1];
    uint2* outp = reinterpret_cast<uint2*>(g_aggh + base);
    if (beg == end) { uint2 z = {0u, 0u}; *outp = z; return; }

    uint2 qu = *reinterpret_cast<const uint2*>(g_qh + base);
    float2 qa = __half22float2(*reinterpret_cast<const __half2*>(&qu.x));
    float2 qb = __half22float2(*reinterpret_cast<const __half2*>(&qu.y));
    const float sc = 0.17677669529663687f;
    float q0 = qa.x * sc, q1 = qa.y * sc, q2 = qb.x * sc, q3 = qb.y * sc;

    float l = 0.f, a0 = 0.f, a1 = 0.f, a2 = 0.f, a3 = 0.f;
    int hoff = head * kDH + d0;

    {
        uint2 ku = *reinterpret_cast<const uint2*>(g_kh + base);
        uint2 vu = *reinterpret_cast<const uint2*>(g_vh + base);
        float2 ka = __half22float2(*reinterpret_cast<const __half2*>(&ku.x));
        float2 kb = __half22float2(*reinterpret_cast<const __half2*>(&ku.y));
        float s = q0 * ka.x + q1 * ka.y + q2 * kb.x + q3 * kb.y;
        s += __shfl_xor_sync(~0u, s, 4);
        s += __shfl_xor_sync(~0u, s, 2);
        s += __shfl_xor_sync(~0u, s, 1);
        float p = __expf(s);
        float2 va = __half22float2(*reinterpret_cast<const __half2*>(&vu.x));
        float2 vb = __half22float2(*reinterpret_cast<const __half2*>(&vu.y));
        l += p; a0 += p * va.x; a1 += p * va.y; a2 += p * vb.x; a3 += p * vb.y;
    }
    int i = beg;
    for (; i + 1 < end; i += 2) {
        int s0 = g_csr[i], s1 = g_csr[i + 1];
        const __half* k0p = g_kh + (size_t)s0 * kTD + hoff;
        const __half* k1p = g_kh + (size_t)s1 * kTD + hoff;
        const __half* v0p = g_vh + (size_t)s0 * kTD + hoff;
        const __half* v1p = g_vh + (size_t)s1 * kTD + hoff;
        uint2 k0u = *reinterpret_cast<const uint2*>(k0p);
        uint2 k1u = *reinterpret_cast<const uint2*>(k1p);
        uint2 v0u = *reinterpret_cast<const uint2*>(v0p);
        uint2 v1u = *reinterpret_cast<const uint2*>(v1p);
        float2 k0a = __half22float2(*reinterpret_cast<const __half2*>(&k0u.x));
        float2 k0b = __half22float2(*reinterpret_cast<const __half2*>(&k0u.y));
        float2 k1a = __half22float2(*reinterpret_cast<const __half2*>(&k1u.x));
        float2 k1b = __half22float2(*reinterpret_cast<const __half2*>(&k1u.y));
        float sa = q0 * k0a.x + q1 * k0a.y + q2 * k0b.x + q3 * k0b.y;
        float sb = q0 * k1a.x + q1 * k1a.y + q2 * k1b.x + q3 * k1b.y;
        sa += __shfl_xor_sync(~0u, sa, 4); sb += __shfl_xor_sync(~0u, sb, 4);
        sa += __shfl_xor_sync(~0u, sa, 2); sb += __shfl_xor_sync(~0u, sb, 2);
        sa += __shfl_xor_sync(~0u, sa, 1); sb += __shfl_xor_sync(~0u, sb, 1);
        float p0 = __expf(sa), p1 = __expf(sb);
        float2 v0a = __half22float2(*reinterpret_cast<const __half2*>(&v0u.x));
        float2 v0b = __half22float2(*reinterpret_cast<const __half2*>(&v0u.y));
        float2 v1a = __half22float2(*reinterpret_cast<const __half2*>(&v1u.x));
        float2 v1b = __half22float2(*reinterpret_cast<const __half2*>(&v1u.y));
        l += p0 + p1;
        a0 += p0 * v0a.x + p1 * v1a.x;
        a1 += p0 * v0a.y + p1 * v1a.y;
        a2 += p0 * v0b.x + p1 * v1b.x;
        a3 += p0 * v0b.y + p1 * v1b.y;
    }
    if (i < end) {
        int s0 = g_csr[i];
        const __half* kp = g_kh + (size_t)s0 * kTD + hoff;
        const __half* vp = g_vh + (size_t)s0 * kTD + hoff;
        uint2 ku = *reinterpret_cast<const uint2*>(kp);
        uint2 vu = *reinterpret_cast<const uint2*>(vp);
        float2 ka = __half22float2(*reinterpret_cast<const __half2*>(&ku.x));
        float2 kb = __half22float2(*reinterpret_cast<const __half2*>(&ku.y));
        float s = q0 * ka.x + q1 * ka.y + q2 * kb.x + q3 * kb.y;
        s += __shfl_xor_sync(~0u, s, 4);
        s += __shfl_xor_sync(~0u, s, 2);
        s += __shfl_xor_sync(~0u, s, 1);
        float p = __expf(s);
        float2 va = __half22float2(*reinterpret_cast<const __half2*>(&vu.x));
        float2 vb = __half22float2(*reinterpret_cast<const __half2*>(&vu.y));
        l += p; a0 += p * va.x; a1 += p * va.y; a2 += p * vb.x; a3 += p * vb.y;
    }
    float inv = 1.f / l;
    __half2 o0 = __floats2half2_rn(a0 * inv, a1 * inv);
    __half2 o1 = __floats2half2_rn(a2 * inv, a3 * inv);
    uint2 ou = {*reinterpret_cast<uint32_t*>(&o0), *reinterpret_cast<uint32_t*>(&o1)};
    *outp = ou;
}

// ---------------- host ----------------
static inline void gemm_s(cudaStream_t st, const __half* A, const __half* Bt,
                          const float* bias, float* C, __half* aux, __half* aux2,
                          int M, int N, int K, int flags) {
    dim3 g(N / BN, M / BM);
    gemm_tc<0><<<g, 256, DSMEM, st>>>(A, Bt, bias, C, aux, aux2, M, N, K, flags);
}
static inline void gemm_f32A(cudaStream_t st, const float* A, const __half* Bt,
                             const float* bias, float* C,
                             int M, int N, int K, int flags) {
    dim3 g(N / BN, M / BM);
    gemm_tc<1><<<g, 256, DSMEM, st>>>(A, Bt, bias, C, nullptr, nullptr, M, N, K, flags);
}

extern "C" void kernel_launch(void* const* d_in, const int* in_sizes, int n_in,
                              void* d_out, int out_size) {
    const float* x     = (const float*)d_in[0];
    const int*   ei    = (const int*)  d_in[1];
    const float* w_in  = (const float*)d_in[2];
    const float* b_in  = (const float*)d_in[3];
    const float* ln1_g = (const float*)d_in[4];
    const float* ln1_b = (const float*)d_in[5];
    const float* ln2_g = (const float*)d_in[6];
    const float* ln2_b = (const float*)d_in[7];
    const float* wq = (const float*)d_in[8];  const float* bq = (const float*)d_in[9];
    const float* wk = (const float*)d_in[10]; const float* bk = (const float*)d_in[11];
    const float* wv = (const float*)d_in[12]; const float* bv = (const float*)d_in[13];
    const float* wo = (const float*)d_in[14]; const float* bo = (const float*)d_in[15];
    const float* w1 = (const float*)d_in[16]; const float* b1 = (const float*)d_in[17];
    const float* w2 = (const float*)d_in[18]; const float* b2 = (const float*)d_in[19];
    float* h = (float*)d_out;

    cudaFuncSetAttribute(gemm_tc<0>, cudaFuncAttributeMaxDynamicSharedMemorySize, DSMEM);
    cudaFuncSetAttribute(gemm_tc<1>, cudaFuncAttributeMaxDynamicSharedMemorySize, DSMEM);

    __half *xnh, *qh, *kh, *vh, *aggh, *ffnh, *winT, *wqkvT, *woT, *w1T, *w2T;
    float *bqkv;
    int *deg, *fill;
    cudaGetSymbolAddress((void**)&xnh,   g_xnh);
    cudaGetSymbolAddress((void**)&qh,    g_qh);
    cudaGetSymbolAddress((void**)&kh,    g_kh);
    cudaGetSymbolAddress((void**)&vh,    g_vh);
    cudaGetSymbolAddress((void**)&aggh,  g_aggh);
    cudaGetSymbolAddress((void**)&ffnh,  g_ffnh);
    cudaGetSymbolAddress((void**)&winT,  g_winT);
    cudaGetSymbolAddress((void**)&wqkvT, g_wqkvT);
    cudaGetSymbolAddress((void**)&woT,   g_woT);
    cudaGetSymbolAddress((void**)&w1T,   g_w1T);
    cudaGetSymbolAddress((void**)&w2T,   g_w2T);
    cudaGetSymbolAddress((void**)&bqkv,  g_bqkv);
    cudaGetSymbolAddress((void**)&deg,   g_deg);
    cudaGetSymbolAddress((void**)&fill,  g_fill);

    // Streams/events created ONCE (first, non-captured correctness call) and
    // reused every call — resources live in the pre-capture baseline.
    static cudaStream_t sB = nullptr, sC = nullptr;
    static cudaEvent_t ev0 = nullptr, evB = nullptr, evC1 = nullptr, evC2 = nullptr, evW = nullptr;
    if (sB == nullptr) {
        cudaStreamCreateWithFlags(&sB, cudaStreamNonBlocking);
        cudaStreamCreateWithFlags(&sC, cudaStreamNonBlocking);
        cudaEventCreateWithFlags(&ev0, cudaEventDisableTiming);
        cudaEventCreateWithFlags(&evB, cudaEventDisableTiming);
        cudaEventCreateWithFlags(&evC1, cudaEventDisableTiming);
        cudaEventCreateWithFlags(&evC2, cudaEventDisableTiming);
        cudaEventCreateWithFlags(&evW, cudaEventDisableTiming);
    }

    cudaEventRecord(ev0, 0);
    cudaStreamWaitEvent(sB, ev0, 0);
    cudaStreamWaitEvent(sC, ev0, 0);

    // ---- stream B: winT (needed by input proj) then CSR build ----
    {
        dim3 b(32, 8);
        transpose_h<<<dim3(kD / 32, kD / 32), b, 0, sB>>>(w_in, winT, kD, kD);
        cudaEventRecord(evW, sB);
    }
    cudaMemsetAsync(deg,  0, kN * sizeof(int), sB);
    cudaMemsetAsync(fill, 0, kN * sizeof(int), sB);
    deg_count_kernel<<<kE / 256, 256, 0, sB>>>(ei);
    prefix_kernel<<<1, 1024, 0, sB>>>();
    scatter_kernel<<<kE / 256, 256, 0, sB>>>(ei);
    cudaEventRecord(evB, sB);

    // ---- stream C: qkvT(l0)+bias first, then the rest ----
    {
        dim3 b(32, 8);
        transpose3_h<<<dim3(kTD / 32, kD / 32, 3), b, 0, sC>>>(wq, wk, wv, wqkvT, kD, kTD);
        pack_bias<<<kL * kQKV / 256, 256, 0, sC>>>(bq, bk, bv);
        cudaEventRecord(evC1, sC);
        transpose_h<<<dim3(kD / 32, kTD / 32), b, 0, sC>>>(wo, woT, kTD, kD);
        transpose_h<<<dim3(kFFN / 32, kD / 32), b, 0, sC>>>(w1, w1T, kD, kFFN);
        transpose_h<<<dim3(kD / 32, kFFN / 32), b, 0, sC>>>(w2, w2T, kFFN, kD);
        transpose3_h<<<dim3(kTD / 32, kD / 32, 3), b, 0, sC>>>(
            wq + (size_t)kD * kTD, wk + (size_t)kD * kTD, wv + (size_t)kD * kTD,
            wqkvT + (size_t)kQKV * kD, kD, kTD);
        transpose_h<<<dim3(kD / 32, kTD / 32), b, 0, sC>>>(wo + (size_t)kTD * kD,
                                                           woT + (size_t)kD * kTD, kTD, kD);
        transpose_h<<<dim3(kFFN / 32, kD / 32), b, 0, sC>>>(w1 + (size_t)kD * kFFN,
                                                            w1T + (size_t)kFFN * kD, kD, kFFN);
        transpose_h<<<dim3(kD / 32, kFFN / 32), b, 0, sC>>>(w2 + (size_t)kFFN * kD,
                                                            w2T + (size_t)kD * kFFN, kFFN, kD);
        cudaEventRecord(evC2, sC);
    }

    // ---- default stream: main chain (input proj reads fp32 x directly) ----
    cudaStreamWaitEvent(0, evW, 0);
    gemm_f32A(0, x, winT, b_in, h, kN, kD, kD, 0);

    for (int l = 0; l < kL; ++l) {
        ln_kernel<<<kN / 8, 256>>>(h, ln1_g + l * kD, ln1_b + l * kD, xnh);
        if (l == 0) cudaStreamWaitEvent(0, evC1, 0);
        gemm_s(0, xnh, wqkvT + (size_t)l * kQKV * kD, bqkv + (size_t)l * kQKV,
               (float*)qh, kh, vh, kN, kQKV, kD, 3);
        if (l == 0) cudaStreamWaitEvent(0, evB, 0);
        attn_kernel<<<kN / 4, 256>>>();
        if (l == 0) cudaStreamWaitEvent(0, evC2, 0);
        gemm_s(0, aggh, woT + (size_t)l * kD * kTD, bo + (size_t)l * kD,
               h, nullptr, nullptr, kN, kD, kTD, 1);
        ln_kernel<<<kN / 8, 256>>>(h, ln2_g + l * kD, ln2_b + l * kD, xnh);
        gemm_s(0, xnh, w1T + (size_t)l * kFFN * kD, b1 + (size_t)l * kFFN,
               nullptr, ffnh, nullptr, kN, kFFN, kD, 2);
        gemm_s(0, ffnh, w2T + (size_t)l * kD * kFFN, b2 + (size_t)l * kD,
               h, nullptr, nullptr, kN, kD, kFFN, 1);
    }
}

// round 17
// speedup vs baseline: 1.1889x; 1.0191x over previous
#include <cuda_runtime.h>
#include <cuda_fp16.h>
#include <math.h>
#include <stdint.h>

#define kN   32768
#define kE   (kN * 16)
#define kD   256
#define kH   8
#define kDH  32
#define kTD  256
#define kFFN 1024
#define kL   2
#define kQKV 768

// ---------------- device scratch ----------------
__device__ __half  g_xnh [kN * kD];
__device__ __half  g_qh  [kN * kTD];
__device__ uint8_t g_k8  [kN * kTD];      // keys in fp8 e4m3
__device__ __half  g_vh  [kN * kTD];
__device__ __half  g_aggh[kN * kTD];
__device__ __half  g_ffnh[kN * kFFN];
__device__ __half  g_winT [kD * kD];
__device__ __half  g_wqkvT[kL * kQKV * kD];
__device__ __half  g_woT  [kL * kD * kTD];
__device__ __half  g_w1T  [kL * kFFN * kD];
__device__ __half  g_w2T  [kL * kD * kFFN];
__device__ float   g_bqkv [kL * kQKV];
__device__ int     g_deg [kN];
__device__ int     g_fill[kN];
__device__ int     g_off [kN + 1];
__device__ int     g_csr [kE];

// ---------------- helpers ----------------
__device__ __forceinline__ uint32_t smem_u32(const void* p) {
    uint32_t a;
    asm("{ .reg .u64 t; cvta.to.shared.u64 t, %1; cvt.u32.u64 %0, t; }" : "=r"(a) : "l"(p));
    return a;
}
__device__ __forceinline__ void mma_f16(float& d0, float& d1, float& d2, float& d3,
                                        uint32_t a0, uint32_t a1, uint32_t a2, uint32_t a3,
                                        uint32_t b0, uint32_t b1) {
    asm volatile("mma.sync.aligned.m16n8k16.row.col.f32.f16.f16.f32 "
                 "{%0,%1,%2,%3}, {%4,%5,%6,%7}, {%8,%9}, {%0,%1,%2,%3};"
                 : "+f"(d0), "+f"(d1), "+f"(d2), "+f"(d3)
                 : "r"(a0), "r"(a1), "r"(a2), "r"(a3), "r"(b0), "r"(b1));
}
__device__ __forceinline__ void ldsm_x4(uint4& r, uint32_t addr) {
    asm volatile("ldmatrix.sync.aligned.m8n8.x4.shared.b16 {%0,%1,%2,%3}, [%4];"
                 : "=r"(r.x), "=r"(r.y), "=r"(r.z), "=r"(r.w) : "r"(addr));
}
__device__ __forceinline__ void cp16(uint32_t saddr, const void* gaddr) {
    asm volatile("cp.async.cg.shared.global [%0], [%1], 16;" :: "r"(saddr), "l"(gaddr));
}
__device__ __forceinline__ void sts16(uint32_t saddr, uint32_t a, uint32_t b, uint32_t c, uint32_t d) {
    asm volatile("st.shared.v4.b32 [%0], {%1,%2,%3,%4};" :: "r"(saddr), "r"(a), "r"(b), "r"(c), "r"(d) : "memory");
}
__device__ __forceinline__ uint32_t pack_h2f(float lo, float hi) {
    __half2 h = __floats2half2_rn(lo, hi);
    return *reinterpret_cast<uint32_t*>(&h);
}
// pack two floats into e4m3x2 (lo = first arg)
__device__ __forceinline__ uint16_t pack_e4m3x2(float lo, float hi) {
    uint16_t r;
    asm("cvt.rn.satfinite.e4m3x2.f32 %0, %1, %2;" : "=h"(r) : "f"(hi), "f"(lo));
    return r;
}
// widen e4m3x2 -> float2 (element order preserved)
__device__ __forceinline__ float2 e4m3x2_to_f2(uint16_t s) {
    uint32_t h;
    asm("cvt.rn.f16x2.e4m3x2 %0, %1;" : "=r"(h) : "h"(s));
    return __half22float2(*reinterpret_cast<__half2*>(&h));
}
__device__ __forceinline__ float gelu_exact(float x) {
    return 0.5f * x * (1.f + erff(x * 0.7071067811865475f));
}

// ---------------- fp16 cp.async+ldmatrix GEMM: C = A[M,K] @ Bt[N,K]^T -----
#define BM 128
#define BN 128
#define BK 32
#define ATILE_B (BM * BK * 2)
#define STAGE_B (ATILE_B + BN * BK * 2)
#define NSTAGE 4
#define DSMEM (NSTAGE * STAGE_B)

template <int AF32>
__global__ void __launch_bounds__(256, 2)
gemm_tc(const void* __restrict__ Av, const __half* __restrict__ Bt,
        const float* __restrict__ bias, float* __restrict__ C,
        __half* __restrict__ aux, uint8_t* __restrict__ aux2,
        int M, int N, int K, int flags) {
    extern __shared__ char dsm[];
    uint32_t sbase = smem_u32(dsm);

    int tid = threadIdx.x;
    int lane = tid & 31;
    int wid = tid >> 5;
    int warp_row = wid >> 2;
    int warp_col = wid & 3;
    int row0 = blockIdx.y * BM, col0 = blockIdx.x * BN;

    const __half* Agh = (const __half*)Av + (size_t)row0 * K;
    const float*  Agf = (const float*)Av + (size_t)row0 * K;
    const __half* Bg  = Bt + (size_t)col0 * K;

    int id0 = tid * 2;
    int crow0 = id0 >> 2,       cc0 = id0 & 3;
    int crow1 = (id0 + 1) >> 2, cc1 = (id0 + 1) & 3;
    int cs0 = cc0 ^ ((crow0 >> 1) & 3);
    int cs1 = cc1 ^ ((crow1 >> 1) & 3);
    uint32_t sA0 = crow0 * 64 + cs0 * 16;
    uint32_t sA1 = crow1 * 64 + cs1 * 16;
    size_t gA0 = (size_t)crow0 * K + cc0 * 8;
    size_t gA1 = (size_t)crow1 * K + cc1 * 8;

    int lane_r = lane & 15;
    int lane_c = lane >> 4;
    int xorv = (lane_r >> 1) & 3;

    float acc[4][4][4];
    #pragma unroll
    for (int i = 0; i < 4; ++i)
        #pragma unroll
        for (int j = 0; j < 4; ++j)
            #pragma unroll
            for (int q = 0; q < 4; ++q) acc[i][j][q] = 0.f;

    int nIter = K / BK;
    float4 pf[4];

    #pragma unroll
    for (int s = 0; s < 3; ++s) {
        uint32_t Ab = sbase + s * STAGE_B;
        uint32_t Bb = Ab + ATILE_B;
        int kk = s * BK;
        if (AF32) {
            float4 u0 = *reinterpret_cast<const float4*>(Agf + gA0 + kk);
            float4 u1 = *reinterpret_cast<const float4*>(Agf + gA0 + kk + 4);
            float4 u2 = *reinterpret_cast<const float4*>(Agf + gA1 + kk);
            float4 u3 = *reinterpret_cast<const float4*>(Agf + gA1 + kk + 4);
            sts16(Ab + sA0, pack_h2f(u0.x, u0.y), pack_h2f(u0.z, u0.w),
                             pack_h2f(u1.x, u1.y), pack_h2f(u1.z, u1.w));
            sts16(Ab + sA1, pack_h2f(u2.x, u2.y), pack_h2f(u2.z, u2.w),
                             pack_h2f(u3.x, u3.y), pack_h2f(u3.z, u3.w));
        } else {
            cp16(Ab + sA0, Agh + gA0 + kk);
            cp16(Ab + sA1, Agh + gA1 + kk);
        }
        cp16(Bb + sA0, Bg + gA0 + kk);
        cp16(Bb + sA1, Bg + gA1 + kk);
        asm volatile("cp.async.commit_group;");
    }

    for (int it = 0; it < nIter; ++it) {
        bool more = (it + 3 < nIter);
        if (AF32 && more) {
            int kk = (it + 3) * BK;
            pf[0] = *reinterpret_cast<const float4*>(Agf + gA0 + kk);
            pf[1] = *reinterpret_cast<const float4*>(Agf + gA0 + kk + 4);
            pf[2] = *reinterpret_cast<const float4*>(Agf + gA1 + kk);
            pf[3] = *reinterpret_cast<const float4*>(Agf + gA1 + kk + 4);
        }
        asm volatile("cp.async.wait_group 2;");
        __syncthreads();
        uint32_t Ab = sbase + (it & 3) * STAGE_B;
        uint32_t Bb = Ab + ATILE_B;

        #pragma unroll
        for (int kc = 0; kc < 2; ++kc) {
            uint32_t cs = (uint32_t)(((kc * 2 + lane_c) ^ xorv) * 16);
            uint4 af[4], bm[2];
            #pragma unroll
            for (int mt = 0; mt < 4; ++mt)
                ldsm_x4(af[mt], Ab + (uint32_t)(warp_row * 64 + mt * 16 + lane_r) * 64 + cs);
            #pragma unroll
            for (int ntp = 0; ntp < 2; ++ntp)
                ldsm_x4(bm[ntp], Bb + (uint32_t)(warp_col * 32 + ntp * 16 + lane_r) * 64 + cs);
            #pragma unroll
            for (int mt = 0; mt < 4; ++mt) {
                mma_f16(acc[mt][0][0], acc[mt][0][1], acc[mt][0][2], acc[mt][0][3],
                        af[mt].x, af[mt].y, af[mt].z, af[mt].w, bm[0].x, bm[0].z);
                mma_f16(acc[mt][1][0], acc[mt][1][1], acc[mt][1][2], acc[mt][1][3],
                        af[mt].x, af[mt].y, af[mt].z, af[mt].w, bm[0].y, bm[0].w);
                mma_f16(acc[mt][2][0], acc[mt][2][1], acc[mt][2][2], acc[mt][2][3],
                        af[mt].x, af[mt].y, af[mt].z, af[mt].w, bm[1].x, bm[1].z);
                mma_f16(acc[mt][3][0], acc[mt][3][1], acc[mt][3][2], acc[mt][3][3],
                        af[mt].x, af[mt].y, af[mt].z, af[mt].w, bm[1].y, bm[1].w);
            }
        }
        if (more) {
            uint32_t Aw = sbase + ((it + 3) & 3) * STAGE_B;
            uint32_t Bw = Aw + ATILE_B;
            int kk = (it + 3) * BK;
            if (AF32) {
                sts16(Aw + sA0, pack_h2f(pf[0].x, pf[0].y), pack_h2f(pf[0].z, pf[0].w),
                                 pack_h2f(pf[1].x, pf[1].y), pack_h2f(pf[1].z, pf[1].w));
                sts16(Aw + sA1, pack_h2f(pf[2].x, pf[2].y), pack_h2f(pf[2].z, pf[2].w),
                                 pack_h2f(pf[3].x, pf[3].y), pack_h2f(pf[3].z, pf[3].w));
            } else {
                cp16(Aw + sA0, Agh + gA0 + kk);
                cp16(Aw + sA1, Agh + gA1 + kk);
            }
            cp16(Bw + sA0, Bg + gA0 + kk);
            cp16(Bw + sA1, Bg + gA1 + kk);
        }
        asm volatile("cp.async.commit_group;");
    }

    int g = lane >> 2, tg = lane & 3;
    bool isq = (col0 < 256);
    bool isv = (col0 >= 512);
    #pragma unroll
    for (int mt = 0; mt < 4; ++mt) {
        int rbase = row0 + warp_row * 64 + mt * 16 + g;
        #pragma unroll
        for (int nt = 0; nt < 4; ++nt) {
            int c = col0 + warp_col * 32 + nt * 8 + tg * 2;
            float2 bs = *reinterpret_cast<const float2*>(&bias[c]);
            float v0 = acc[mt][nt][0] + bs.x;
            float v1 = acc[mt][nt][1] + bs.y;
            float v2 = acc[mt][nt][2] + bs.x;
            float v3 = acc[mt][nt][3] + bs.y;
            if (flags == 2) {
                v0 = gelu_exact(v0); v1 = gelu_exact(v1);
                v2 = gelu_exact(v2); v3 = gelu_exact(v3);
                *reinterpret_cast<__half2*>(aux + (size_t)rbase * N + c)       = __floats2half2_rn(v0, v1);
                *reinterpret_cast<__half2*>(aux + (size_t)(rbase + 8) * N + c) = __floats2half2_rn(v2, v3);
            } else if (flags == 3) {
                int cm = c & 255;
                if (isq) {
                    __half* dst = reinterpret_cast<__half*>(C);
                    *reinterpret_cast<__half2*>(dst + (size_t)rbase * kTD + cm)       = __floats2half2_rn(v0, v1);
                    *reinterpret_cast<__half2*>(dst + (size_t)(rbase + 8) * kTD + cm) = __floats2half2_rn(v2, v3);
                } else if (isv) {
                    *reinterpret_cast<__half2*>(aux + (size_t)rbase * kTD + cm)       = __floats2half2_rn(v0, v1);
                    *reinterpret_cast<__half2*>(aux + (size_t)(rbase + 8) * kTD + cm) = __floats2half2_rn(v2, v3);
                } else {  // k -> fp8
                    *reinterpret_cast<uint16_t*>(aux2 + (size_t)rbase * kTD + cm)       = pack_e4m3x2(v0, v1);
                    *reinterpret_cast<uint16_t*>(aux2 + (size_t)(rbase + 8) * kTD + cm) = pack_e4m3x2(v2, v3);
                }
            } else {
                float2* cp0 = reinterpret_cast<float2*>(C + (size_t)rbase * N + c);
                float2* cp1 = reinterpret_cast<float2*>(C + (size_t)(rbase + 8) * N + c);
                if (flags == 1) {
                    float2 o0 = *cp0, o1 = *cp1;
                    v0 += o0.x; v1 += o0.y; v2 += o1.x; v3 += o1.y;
                }
                float2 r0 = {v0, v1}, r1 = {v2, v3};
                *cp0 = r0;
                *cp1 = r1;
            }
        }
    }
}

// ---------------- transpose + fp32->fp16 ----------------
__global__ void transpose_h(const float* __restrict__ src, __half* __restrict__ dst,
                            int R, int C) {
    __shared__ float t[32][33];
    int bx = blockIdx.x * 32, by = blockIdx.y * 32;
    int x = bx + threadIdx.x;
    #pragma unroll
    for (int j = 0; j < 32; j += 8)
        t[threadIdx.y + j][threadIdx.x] = src[(size_t)(by + threadIdx.y + j) * C + x];
    __syncthreads();
    int xo = by + threadIdx.x;
    #pragma unroll
    for (int j = 0; j < 32; j += 8)
        dst[(size_t)(bx + threadIdx.y + j) * R + xo] = __float2half_rn(t[threadIdx.x][threadIdx.y + j]);
}
__global__ void transpose3_h(const float* s0, const float* s1, const float* s2,
                             __half* __restrict__ dst, int R, int C) {
    __shared__ float t[32][33];
    const float* src = (blockIdx.z == 0) ? s0 : (blockIdx.z == 1) ? s1 : s2;
    __half* d = dst + (size_t)blockIdx.z * C * R;
    int bx = blockIdx.x * 32, by = blockIdx.y * 32;
    int x = bx + threadIdx.x;
    #pragma unroll
    for (int j = 0; j < 32; j += 8)
        t[threadIdx.y + j][threadIdx.x] = src[(size_t)(by + threadIdx.y + j) * C + x];
    __syncthreads();
    int xo = by + threadIdx.x;
    #pragma unroll
    for (int j = 0; j < 32; j += 8)
        d[(size_t)(bx + threadIdx.y + j) * R + xo] = __float2half_rn(t[threadIdx.x][threadIdx.y + j]);
}

__global__ void pack_bias(const float* bq, const float* bk, const float* bv) {
    int t = blockIdx.x * 256 + threadIdx.x;
    int l = t / kQKV, r = t % kQKV;
    const float* s = (r < 256) ? bq + l * kTD + r
                   : (r < 512) ? bk + l * kTD + (r - 256)
                               : bv + l * kTD + (r - 512);
    g_bqkv[t] = *s;
}

// ---------------- CSR build ----------------
__global__ void deg_count_kernel(const int* __restrict__ ei) {
    int e = blockIdx.x * 256 + threadIdx.x;
    if (e < kE) atomicAdd(&g_deg[ei[kE + e]], 1);
}
__global__ void prefix_kernel() {
    __shared__ int sums[1024];
    int t = threadIdx.x;
    int base = t * 32;
    int s = 0;
    #pragma unroll 4
    for (int i = 0; i < 32; ++i) s += g_deg[base + i];
    sums[t] = s;
    __syncthreads();
    for (int o = 1; o < 1024; o <<= 1) {
        int v = (t >= o) ? sums[t - o] : 0;
        __syncthreads();
        sums[t] += v;
        __syncthreads();
    }
    int run = sums[t] - s;
    for (int i = 0; i < 32; ++i) { g_off[base + i] = run; run += g_deg[base + i]; }
    if (t == 1023) g_off[kN] = run;
}
__global__ void scatter_kernel(const int* __restrict__ ei) {
    int e = blockIdx.x * 256 + threadIdx.x;
    if (e < kE) {
        int d = ei[kE + e];
        int pos = g_off[d] + atomicAdd(&g_fill[d], 1);
        g_csr[pos] = ei[e];
    }
}

// ---------------- LayerNorm: warp per row, fp32 in, fp16 out --------------
__global__ void __launch_bounds__(256)
ln_kernel(const float* __restrict__ x, const float* __restrict__ gg,
          const float* __restrict__ bb, __half* __restrict__ y) {
    int lane = threadIdx.x & 31;
    int row = blockIdx.x * 8 + (threadIdx.x >> 5);
    const float4* xr = reinterpret_cast<const float4*>(x + (size_t)row * kD);
    float4 a0 = xr[lane];
    float4 a1 = xr[lane + 32];
    float s = a0.x + a0.y + a0.z + a0.w + a1.x + a1.y + a1.z + a1.w;
    float q = a0.x*a0.x + a0.y*a0.y + a0.z*a0.z + a0.w*a0.w
            + a1.x*a1.x + a1.y*a1.y + a1.z*a1.z + a1.w*a1.w;
    #pragma unroll
    for (int o = 16; o; o >>= 1) {
        s += __shfl_xor_sync(~0u, s, o);
        q += __shfl_xor_sync(~0u, q, o);
    }
    float mean = s * (1.f / kD);
    float var = q * (1.f / kD) - mean * mean;
    float inv = rsqrtf(var + 1e-5f);
    float4 g0 = reinterpret_cast<const float4*>(gg)[lane];
    float4 g1 = reinterpret_cast<const float4*>(gg)[lane + 32];
    float4 b0 = reinterpret_cast<const float4*>(bb)[lane];
    float4 b1 = reinterpret_cast<const float4*>(bb)[lane + 32];
    __half2 o0 = __floats2half2_rn((a0.x - mean) * inv * g0.x + b0.x, (a0.y - mean) * inv * g0.y + b0.y);
    __half2 o1 = __floats2half2_rn((a0.z - mean) * inv * g0.z + b0.z, (a0.w - mean) * inv * g0.w + b0.w);
    __half2 o2 = __floats2half2_rn((a1.x - mean) * inv * g1.x + b1.x, (a1.y - mean) * inv * g1.y + b1.y);
    __half2 o3 = __floats2half2_rn((a1.z - mean) * inv * g1.z + b1.z, (a1.w - mean) * inv * g1.w + b1.w);
    uint2 u0 = {*reinterpret_cast<uint32_t*>(&o0), *reinterpret_cast<uint32_t*>(&o1)};
    uint2 u1 = {*reinterpret_cast<uint32_t*>(&o2), *reinterpret_cast<uint32_t*>(&o3)};
    *reinterpret_cast<uint2*>(y + (size_t)row * kD + lane * 4)       = u0;
    *reinterpret_cast<uint2*>(y + (size_t)row * kD + 128 + lane * 4) = u1;
}

// ------- Edge attention: warp = 4 heads, lane = 4 dims, fp8 k -------------
__global__ void __launch_bounds__(256)
attn_kernel() {
    int tid = threadIdx.x;
    int lane = tid & 31;
    int wid = tid >> 5;
    int node = blockIdx.x * 4 + (wid >> 1);
    int head = ((wid & 1) << 2) + (lane >> 3);
    int d0 = (lane & 7) << 2;
    int base = node * kTD + head * kDH + d0;

    int beg = g_off[node], end = g_off[node + 1];
    uint2* outp = reinterpret_cast<uint2*>(g_aggh + base);
    if (beg == end) { uint2 z = {0u, 0u}; *outp = z; return; }

    uint2 qu = *reinterpret_cast<const uint2*>(g_qh + base);
    float2 qa = __half22float2(*reinterpret_cast<const __half2*>(&qu.x));
    float2 qb = __half22float2(*reinterpret_cast<const __half2*>(&qu.y));
    const float sc = 0.17677669529663687f;
    float q0 = qa.x * sc, q1 = qa.y * sc, q2 = qb.x * sc, q3 = qb.y * sc;

    float l = 0.f, a0 = 0.f, a1 = 0.f, a2 = 0.f, a3 = 0.f;
    int hoff = head * kDH + d0;

    // self edge
    {
        uint32_t k8 = *reinterpret_cast<const uint32_t*>(g_k8 + base);
        uint2 vu = *reinterpret_cast<const uint2*>(g_vh + base);
        float2 ka = e4m3x2_to_f2((uint16_t)(k8 & 0xffff));
        float2 kb = e4m3x2_to_f2((uint16_t)(k8 >> 16));
        float s = q0 * ka.x + q1 * ka.y + q2 * kb.x + q3 * kb.y;
        s += __shfl_xor_sync(~0u, s, 4);
        s += __shfl_xor_sync(~0u, s, 2);
        s += __shfl_xor_sync(~0u, s, 1);
        float p = __expf(s);
        float2 va = __half22float2(*reinterpret_cast<const __half2*>(&vu.x));
        float2 vb = __half22float2(*reinterpret_cast<const __half2*>(&vu.y));
        l += p; a0 += p * va.x; a1 += p * va.y; a2 += p * vb.x; a3 += p * vb.y;
    }
    int i = beg;
    for (; i + 1 < end; i += 2) {
        int s0 = g_csr[i], s1 = g_csr[i + 1];
        uint32_t k0w = *reinterpret_cast<const uint32_t*>(g_k8 + (size_t)s0 * kTD + hoff);
        uint32_t k1w = *reinterpret_cast<const uint32_t*>(g_k8 + (size_t)s1 * kTD + hoff);
        uint2 v0u = *reinterpret_cast<const uint2*>(g_vh + (size_t)s0 * kTD + hoff);
        uint2 v1u = *reinterpret_cast<const uint2*>(g_vh + (size_t)s1 * kTD + hoff);
        float2 k0a = e4m3x2_to_f2((uint16_t)(k0w & 0xffff));
        float2 k0b = e4m3x2_to_f2((uint16_t)(k0w >> 16));
        float2 k1a = e4m3x2_to_f2((uint16_t)(k1w & 0xffff));
        float2 k1b = e4m3x2_to_f2((uint16_t)(k1w >> 16));
        float sa = q0 * k0a.x + q1 * k0a.y + q2 * k0b.x + q3 * k0b.y;
        float sb = q0 * k1a.x + q1 * k1a.y + q2 * k1b.x + q3 * k1b.y;
        sa += __shfl_xor_sync(~0u, sa, 4); sb += __shfl_xor_sync(~0u, sb, 4);
        sa += __shfl_xor_sync(~0u, sa, 2); sb += __shfl_xor_sync(~0u, sb, 2);
        sa += __shfl_xor_sync(~0u, sa, 1); sb += __shfl_xor_sync(~0u, sb, 1);
        float p0 = __expf(sa), p1 = __expf(sb);
        float2 v0a = __half22float2(*reinterpret_cast<const __half2*>(&v0u.x));
        float2 v0b = __half22float2(*reinterpret_cast<const __half2*>(&v0u.y));
        float2 v1a = __half22float2(*reinterpret_cast<const __half2*>(&v1u.x));
        float2 v1b = __half22float2(*reinterpret_cast<const __half2*>(&v1u.y));
        l += p0 + p1;
        a0 += p0 * v0a.x + p1 * v1a.x;
        a1 += p0 * v0a.y + p1 * v1a.y;
        a2 += p0 * v0b.x + p1 * v1b.x;
        a3 += p0 * v0b.y + p1 * v1b.y;
    }
    if (i < end) {
        int s0 = g_csr[i];
        uint32_t k8 = *reinterpret_cast<const uint32_t*>(g_k8 + (size_t)s0 * kTD + hoff);
        uint2 vu = *reinterpret_cast<const uint2*>(g_vh + (size_t)s0 * kTD + hoff);
        float2 ka = e4m3x2_to_f2((uint16_t)(k8 & 0xffff));
        float2 kb = e4m3x2_to_f2((uint16_t)(k8 >> 16));
        float s = q0 * ka.x + q1 * ka.y + q2 * kb.x + q3 * kb.y;
        s += __shfl_xor_sync(~0u, s, 4);
        s += __shfl_xor_sync(~0u, s, 2);
        s += __shfl_xor_sync(~0u, s, 1);
        float p = __expf(s);
        float2 va = __half22float2(*reinterpret_cast<const __half2*>(&vu.x));
        float2 vb = __half22float2(*reinterpret_cast<const __half2*>(&vu.y));
        l += p; a0 += p * va.x; a1 += p * va.y; a2 += p * vb.x; a3 += p * vb.y;
    }
    float inv = 1.f / l;
    __half2 o0 = __floats2half2_rn(a0 * inv, a1 * inv);
    __half2 o1 = __floats2half2_rn(a2 * inv, a3 * inv);
    uint2 ou = {*reinterpret_cast<uint32_t*>(&o0), *reinterpret_cast<uint32_t*>(&o1)};
    *outp = ou;
}

// ---------------- host ----------------
static inline void gemm_s(cudaStream_t st, const __half* A, const __half* Bt,
                          const float* bias, float* C, __half* aux, uint8_t* aux2,
                          int M, int N, int K, int flags) {
    dim3 g(N / BN, M / BM);
    gemm_tc<0><<<g, 256, DSMEM, st>>>(A, Bt, bias, C, aux, aux2, M, N, K, flags);
}
static inline void gemm_f32A(cudaStream_t st, const float* A, const __half* Bt,
                             const float* bias, float* C,
                             int M, int N, int K, int flags) {
    dim3 g(N / BN, M / BM);
    gemm_tc<1><<<g, 256, DSMEM, st>>>(A, Bt, bias, C, nullptr, nullptr, M, N, K, flags);
}

extern "C" void kernel_launch(void* const* d_in, const int* in_sizes, int n_in,
                              void* d_out, int out_size) {
    const float* x     = (const float*)d_in[0];
    const int*   ei    = (const int*)  d_in[1];
    const float* w_in  = (const float*)d_in[2];
    const float* b_in  = (const float*)d_in[3];
    const float* ln1_g = (const float*)d_in[4];
    const float* ln1_b = (const float*)d_in[5];
    const float* ln2_g = (const float*)d_in[6];
    const float* ln2_b = (const float*)d_in[7];
    const float* wq = (const float*)d_in[8];  const float* bq = (const float*)d_in[9];
    const float* wk = (const float*)d_in[10]; const float* bk = (const float*)d_in[11];
    const float* wv = (const float*)d_in[12]; const float* bv = (const float*)d_in[13];
    const float* wo = (const float*)d_in[14]; const float* bo = (const float*)d_in[15];
    const float* w1 = (const float*)d_in[16]; const float* b1 = (const float*)d_in[17];
    const float* w2 = (const float*)d_in[18]; const float* b2 = (const float*)d_in[19];
    float* h = (float*)d_out;

    cudaFuncSetAttribute(gemm_tc<0>, cudaFuncAttributeMaxDynamicSharedMemorySize, DSMEM);
    cudaFuncSetAttribute(gemm_tc<1>, cudaFuncAttributeMaxDynamicSharedMemorySize, DSMEM);

    __half *xnh, *qh, *vh, *aggh, *ffnh, *winT, *wqkvT, *woT, *w1T, *w2T;
    uint8_t *k8;
    float *bqkv;
    int *deg, *fill;
    cudaGetSymbolAddress((void**)&xnh,   g_xnh);
    cudaGetSymbolAddress((void**)&qh,    g_qh);
    cudaGetSymbolAddress((void**)&k8,    g_k8);
    cudaGetSymbolAddress((void**)&vh,    g_vh);
    cudaGetSymbolAddress((void**)&aggh,  g_aggh);
    cudaGetSymbolAddress((void**)&ffnh,  g_ffnh);
    cudaGetSymbolAddress((void**)&winT,  g_winT);
    cudaGetSymbolAddress((void**)&wqkvT, g_wqkvT);
    cudaGetSymbolAddress((void**)&woT,   g_woT);
    cudaGetSymbolAddress((void**)&w1T,   g_w1T);
    cudaGetSymbolAddress((void**)&w2T,   g_w2T);
    cudaGetSymbolAddress((void**)&bqkv,  g_bqkv);
    cudaGetSymbolAddress((void**)&deg,   g_deg);
    cudaGetSymbolAddress((void**)&fill,  g_fill);

    // Streams/events created ONCE (first, non-captured correctness call) and
    // reused every call — resources live in the pre-capture baseline.
    static cudaStream_t sB = nullptr, sC = nullptr;
    static cudaEvent_t ev0 = nullptr, evB = nullptr, evC1 = nullptr, evC2 = nullptr, evW = nullptr;
    if (sB == nullptr) {
        cudaStreamCreateWithFlags(&sB, cudaStreamNonBlocking);
        cudaStreamCreateWithFlags(&sC, cudaStreamNonBlocking);
        cudaEventCreateWithFlags(&ev0, cudaEventDisableTiming);
        cudaEventCreateWithFlags(&evB, cudaEventDisableTiming);
        cudaEventCreateWithFlags(&evC1, cudaEventDisableTiming);
        cudaEventCreateWithFlags(&evC2, cudaEventDisableTiming);
        cudaEventCreateWithFlags(&evW, cudaEventDisableTiming);
    }

    cudaEventRecord(ev0, 0);
    cudaStreamWaitEvent(sB, ev0, 0);
    cudaStreamWaitEvent(sC, ev0, 0);

    // ---- stream B: winT (needed by input proj) then CSR build ----
    {
        dim3 b(32, 8);
        transpose_h<<<dim3(kD / 32, kD / 32), b, 0, sB>>>(w_in, winT, kD, kD);
        cudaEventRecord(evW, sB);
    }
    cudaMemsetAsync(deg,  0, kN * sizeof(int), sB);
    cudaMemsetAsync(fill, 0, kN * sizeof(int), sB);
    deg_count_kernel<<<kE / 256, 256, 0, sB>>>(ei);
    prefix_kernel<<<1, 1024, 0, sB>>>();
    scatter_kernel<<<kE / 256, 256, 0, sB>>>(ei);
    cudaEventRecord(evB, sB);

    // ---- stream C: qkvT(l0)+bias first, then the rest ----
    {
        dim3 b(32, 8);
        transpose3_h<<<dim3(kTD / 32, kD / 32, 3), b, 0, sC>>>(wq, wk, wv, wqkvT, kD, kTD);
        pack_bias<<<kL * kQKV / 256, 256, 0, sC>>>(bq, bk, bv);
        cudaEventRecord(evC1, sC);
        transpose_h<<<dim3(kD / 32, kTD / 32), b, 0, sC>>>(wo, woT, kTD, kD);
        transpose_h<<<dim3(kFFN / 32, kD / 32), b, 0, sC>>>(w1, w1T, kD, kFFN);
        transpose_h<<<dim3(kD / 32, kFFN / 32), b, 0, sC>>>(w2, w2T, kFFN, kD);
        transpose3_h<<<dim3(kTD / 32, kD / 32, 3), b, 0, sC>>>(
            wq + (size_t)kD * kTD, wk + (size_t)kD * kTD, wv + (size_t)kD * kTD,
            wqkvT + (size_t)kQKV * kD, kD, kTD);
        transpose_h<<<dim3(kD / 32, kTD / 32), b, 0, sC>>>(wo + (size_t)kTD * kD,
                                                           woT + (size_t)kD * kTD, kTD, kD);
        transpose_h<<<dim3(kFFN / 32, kD / 32), b, 0, sC>>>(w1 + (size_t)kD * kFFN,
                                                            w1T + (size_t)kFFN * kD, kD, kFFN);
        transpose_h<<<dim3(kD / 32, kFFN / 32), b, 0, sC>>>(w2 + (size_t)kFFN * kD,
                                                            w2T + (size_t)kD * kFFN, kFFN, kD);
        cudaEventRecord(evC2, sC);
    }

    // ---- default stream: main chain (input proj reads fp32 x directly) ----
    cudaStreamWaitEvent(0, evW, 0);
    gemm_f32A(0, x, winT, b_in, h, kN, kD, kD, 0);

    for (int l = 0; l < kL; ++l) {
        ln_kernel<<<kN / 8, 256>>>(h, ln1_g + l * kD, ln1_b + l * kD, xnh);
        if (l == 0) cudaStreamWaitEvent(0, evC1, 0);
        gemm_s(0, xnh, wqkvT + (size_t)l * kQKV * kD, bqkv + (size_t)l * kQKV,
               (float*)qh, vh, k8, kN, kQKV, kD, 3);
        if (l == 0) cudaStreamWaitEvent(0, evB, 0);
        attn_kernel<<<kN / 4, 256>>>();
        if (l == 0) cudaStreamWaitEvent(0, evC2, 0);
        gemm_s(0, aggh, woT + (size_t)l * kD * kTD, bo + (size_t)l * kD,
               h, nullptr, nullptr, kN, kD, kTD, 1);
        ln_kernel<<<kN / 8, 256>>>(h, ln2_g + l * kD, ln2_b + l * kD, xnh);
        gemm_s(0, xnh, w1T + (size_t)l * kFFN * kD, b1 + (size_t)l * kFFN,
               nullptr, ffnh, nullptr, kN, kFFN, kD, 2);
        gemm_s(0, ffnh, w2T + (size_t)l * kD * kFFN, b2 + (size_t)l * kD,
               h, nullptr, nullptr, kN, kD, kFFN, 1);
    }
}